// round 1
// baseline (speedup 1.0000x reference)
#include <cuda_runtime.h>
#include <cstdint>

#define B_    16
#define N_    512
#define INF_  256
#define OUTF_ 256
#define H_    8
#define HD_   32
#define NET_  50
#define LOG2E 1.4426950408889634f

// Scratch (allocation-free rule: __device__ globals)
__device__ float g_Wh[B_ * N_ * OUTF_];          // 8 MB
__device__ float g_s1[B_ * N_ * H_];             // pre-scaled by log2e
__device__ float g_s2[B_ * N_ * H_];
__device__ unsigned char g_codes[B_ * N_ * N_];  // et | (adj?0:64)

// ---------------------------------------------------------------------------
// fast exp(e) computed as 2^(y), y already = e * log2e. FMA-pipe only (no MUFU).
// ---------------------------------------------------------------------------
__device__ __forceinline__ float fast_exp2(float y) {
    y = fminf(fmaxf(y, -125.0f), 125.0f);
    float z  = y + 12582912.0f;        // 1.5*2^23 : round-to-nearest
    float kf = z - 12582912.0f;
    float f  = y - kf;                 // f in [-0.5, 0.5]
    float p  = 1.3333558146e-3f;
    p = fmaf(p, f, 9.6181291918e-3f);
    p = fmaf(p, f, 5.5504108664e-2f);
    p = fmaf(p, f, 2.4022650696e-1f);
    p = fmaf(p, f, 6.9314718056e-1f);
    p = fmaf(p, f, 1.0f);
    // low 9 bits of 0x4B400000 are zero -> (zbits<<23) == k<<23 (mod 2^32)
    int ib = __float_as_int(p) + (__float_as_int(z) << 23);
    return __int_as_float(ib);
}

// ---------------------------------------------------------------------------
// K1: pack adj + edge_types -> uint8 codes (code=et if adj else 64)
// ---------------------------------------------------------------------------
__global__ void pack_kernel(const int* __restrict__ adj, const int* __restrict__ et) {
    int idx = blockIdx.x * blockDim.x + threadIdx.x;
    const int total = B_ * N_ * N_ / 4;
    if (idx >= total) return;
    int4 a = ((const int4*)adj)[idx];
    int4 t = ((const int4*)et)[idx];
    uchar4 c;
    c.x = a.x ? (unsigned char)t.x : (unsigned char)64;
    c.y = a.y ? (unsigned char)t.y : (unsigned char)64;
    c.z = a.z ? (unsigned char)t.z : (unsigned char)64;
    c.w = a.w ? (unsigned char)t.w : (unsigned char)64;
    ((uchar4*)g_codes)[idx] = c;
}

// ---------------------------------------------------------------------------
// K2: Wh = x @ W   (M=8192, N=256, K=256)  fp32 tiled GEMM 128x128x16, TM=TN=8
// ---------------------------------------------------------------------------
__global__ __launch_bounds__(256) void gemm_kernel(const float* __restrict__ A,
                                                   const float* __restrict__ Bw) {
    const int M = B_ * N_;  (void)M;
    const int K = INF_, NC = OUTF_;
    __shared__ float As[16][128];
    __shared__ float Bs[16][128];
    const int m0 = blockIdx.y * 128;
    const int n0 = blockIdx.x * 128;
    const int tid = threadIdx.x;
    const int tx = tid & 15, ty = tid >> 4;
    float acc[8][8];
#pragma unroll
    for (int i = 0; i < 8; i++)
#pragma unroll
        for (int j = 0; j < 8; j++) acc[i][j] = 0.f;

    for (int k0 = 0; k0 < K; k0 += 16) {
#pragma unroll
        for (int it = 0; it < 2; it++) {
            int idx = tid + it * 256;
            int row = idx >> 2, c4 = idx & 3;
            float4 v = ((const float4*)A)[(size_t)(m0 + row) * (K / 4) + (k0 >> 2) + c4];
            As[c4 * 4 + 0][row] = v.x;
            As[c4 * 4 + 1][row] = v.y;
            As[c4 * 4 + 2][row] = v.z;
            As[c4 * 4 + 3][row] = v.w;
        }
#pragma unroll
        for (int it = 0; it < 2; it++) {
            int idx = tid + it * 256;
            int row = idx >> 5, c4 = idx & 31;
            ((float4*)&Bs[row][0])[c4] =
                ((const float4*)Bw)[(size_t)(k0 + row) * (NC / 4) + (n0 >> 2) + c4];
        }
        __syncthreads();
#pragma unroll
        for (int k = 0; k < 16; k++) {
            float ra[8], rb[8];
            *(float4*)&ra[0] = *(float4*)&As[k][ty * 8];
            *(float4*)&ra[4] = *(float4*)&As[k][ty * 8 + 4];
            *(float4*)&rb[0] = *(float4*)&Bs[k][tx * 8];
            *(float4*)&rb[4] = *(float4*)&Bs[k][tx * 8 + 4];
#pragma unroll
            for (int i = 0; i < 8; i++)
#pragma unroll
                for (int j = 0; j < 8; j++) acc[i][j] = fmaf(ra[i], rb[j], acc[i][j]);
        }
        __syncthreads();
    }
#pragma unroll
    for (int i = 0; i < 8; i++) {
        int row = m0 + ty * 8 + i;
#pragma unroll
        for (int j4 = 0; j4 < 2; j4++) {
            float4 v = make_float4(acc[i][j4 * 4], acc[i][j4 * 4 + 1],
                                   acc[i][j4 * 4 + 2], acc[i][j4 * 4 + 3]);
            ((float4*)g_Wh)[(size_t)row * (NC / 4) + (n0 >> 2) + tx * 2 + j4] = v;
        }
    }
}

// ---------------------------------------------------------------------------
// K3: s1[row,h] = (Wh[row,h,:] . a1) * log2e ; same for s2. One warp per row.
// ---------------------------------------------------------------------------
__global__ __launch_bounds__(256) void score_kernel(const float* __restrict__ a1,
                                                    const float* __restrict__ a2) {
    __shared__ float a1s[32], a2s[32];
    int tid = threadIdx.x;
    if (tid < 32) { a1s[tid] = a1[tid]; a2s[tid] = a2[tid]; }
    __syncthreads();
    int warp = tid >> 5, lane = tid & 31;
    int row = blockIdx.x * 8 + warp;
    const float4* wh = (const float4*)(g_Wh + (size_t)row * 256);
    float4 v0 = wh[lane * 2];
    float4 v1 = wh[lane * 2 + 1];
    int d0 = (lane * 8) & 31;  // offset within head
    float p1 = v0.x * a1s[d0] + v0.y * a1s[d0 + 1] + v0.z * a1s[d0 + 2] + v0.w * a1s[d0 + 3] +
               v1.x * a1s[d0 + 4] + v1.y * a1s[d0 + 5] + v1.z * a1s[d0 + 6] + v1.w * a1s[d0 + 7];
    float p2 = v0.x * a2s[d0] + v0.y * a2s[d0 + 1] + v0.z * a2s[d0 + 2] + v0.w * a2s[d0 + 3] +
               v1.x * a2s[d0 + 4] + v1.y * a2s[d0 + 5] + v1.z * a2s[d0 + 6] + v1.w * a2s[d0 + 7];
    p1 += __shfl_xor_sync(0xffffffffu, p1, 1);
    p1 += __shfl_xor_sync(0xffffffffu, p1, 2);
    p2 += __shfl_xor_sync(0xffffffffu, p2, 1);
    p2 += __shfl_xor_sync(0xffffffffu, p2, 2);
    if ((lane & 3) == 0) {
        int h = lane >> 2;
        g_s1[(size_t)row * 8 + h] = p1 * LOG2E;
        g_s2[(size_t)row * 8 + h] = p2 * LOG2E;
    }
}

// ---------------------------------------------------------------------------
// K4: fused attention + softmax + aggregation + LayerNorm + ELU
// Block: 512 threads (16 warps); each warp handles 4 consecutive i-rows, all
// heads. Block covers 64 i-rows of one batch. Wh[j] streamed through SMEM in
// 128-j chunks, register-reused across the warp's 4 rows.
//   lane layout (w compute): r = lane>>3 (row 0..3), hw = lane&7 (head)
//   lane layout (accumulate): lane covers dims [8*lane, 8*lane+8) => head lane>>2
// ---------------------------------------------------------------------------
#define CJ 128
__global__ __launch_bounds__(512) void attn_kernel(const float* __restrict__ edge_emb,
                                                   const float* __restrict__ gamma,
                                                   const float* __restrict__ beta,
                                                   float* __restrict__ out) {
    extern __shared__ float sm[];
    float* s2s  = sm;                                   // 4096 floats
    float* embs = sm + 4096;                            // 512 floats (64x8, >=50 zero)
    float* gs   = sm + 4096 + 512;                      // 256
    float* bs   = sm + 4096 + 512 + 256;                // 256
    float* WhS  = sm + 4096 + 512 + 256 + 256;          // CJ*256 = 32768 floats
    unsigned char* codesS = (unsigned char*)(WhS + CJ * 256);  // 64*CJ = 8192 B

    const int b     = blockIdx.y;
    const int iBase = blockIdx.x * 64;
    const int tid   = threadIdx.x;
    const int warp  = tid >> 5, lane = tid & 31;

    // stage s2 for the whole batch, emb table, gamma/beta
    const float* s2g = g_s2 + (size_t)b * N_ * H_;
    for (int idx = tid; idx < N_ * H_; idx += 512) s2s[idx] = s2g[idx];
    {
        float v = 0.f;
        if (tid < NET_ * H_) v = edge_emb[tid] * LOG2E;
        embs[tid] = v;  // 512 threads == 512 entries
    }
    if (tid < 256) { gs[tid] = gamma[tid]; bs[tid] = beta[tid]; }

    const int r  = lane >> 3;   // row within warp's group (w-compute role)
    const int hw = lane & 7;    // head (w-compute role)
    const int hacc = lane >> 2; // head (accumulate role)
    const int iRow = iBase + warp * 4 + r;
    const float s1v = g_s1[((size_t)b * N_ + iRow) * H_ + hw];

    float acc[4][8];
#pragma unroll
    for (int i = 0; i < 4; i++)
#pragma unroll
        for (int k = 0; k < 8; k++) acc[i][k] = 0.f;
    float den = 0.f;

    const int localRow = warp * 4 + r;  // 0..63

    for (int jc = 0; jc < N_; jc += CJ) {
        __syncthreads();
        // Wh chunk [CJ][256] as float4
        const float4* whg = (const float4*)(g_Wh + ((size_t)b * N_ + jc) * 256);
        float4* whs4 = (float4*)WhS;
        for (int idx = tid; idx < CJ * 64; idx += 512) whs4[idx] = whg[idx];
        // codes chunk [64][CJ] (load 4 bytes at a time)
        for (int idx = tid; idx < 64 * (CJ / 4); idx += 512) {
            int rr = idx / (CJ / 4), cc = idx % (CJ / 4);
            const unsigned int* src =
                (const unsigned int*)(g_codes + ((size_t)(b * N_ + iBase + rr)) * N_ + jc);
            ((unsigned int*)codesS)[rr * (CJ / 4) + cc] = src[cc];
        }
        __syncthreads();

#pragma unroll 2
        for (int jj = 0; jj < CJ; jj++) {
            int code = codesS[localRow * CJ + jj];
            float x = s1v + s2s[(jc + jj) * 8 + hw] + embs[(code & 63) * 8 + hw];
            x = fmaxf(x, 0.2f * x);          // leaky_relu (scale commutes)
            float w = fast_exp2(x);
            w = (code < 64) ? w : 0.0f;      // adjacency mask
            den += w;
            float w0 = __shfl_sync(0xffffffffu, w, hacc);
            float w1 = __shfl_sync(0xffffffffu, w, 8 + hacc);
            float w2 = __shfl_sync(0xffffffffu, w, 16 + hacc);
            float w3 = __shfl_sync(0xffffffffu, w, 24 + hacc);
            float4 v0 = ((const float4*)WhS)[jj * 64 + lane * 2];
            float4 v1 = ((const float4*)WhS)[jj * 64 + lane * 2 + 1];
            acc[0][0] = fmaf(w0, v0.x, acc[0][0]);
            acc[0][1] = fmaf(w0, v0.y, acc[0][1]);
            acc[0][2] = fmaf(w0, v0.z, acc[0][2]);
            acc[0][3] = fmaf(w0, v0.w, acc[0][3]);
            acc[0][4] = fmaf(w0, v1.x, acc[0][4]);
            acc[0][5] = fmaf(w0, v1.y, acc[0][5]);
            acc[0][6] = fmaf(w0, v1.z, acc[0][6]);
            acc[0][7] = fmaf(w0, v1.w, acc[0][7]);
            acc[1][0] = fmaf(w1, v0.x, acc[1][0]);
            acc[1][1] = fmaf(w1, v0.y, acc[1][1]);
            acc[1][2] = fmaf(w1, v0.z, acc[1][2]);
            acc[1][3] = fmaf(w1, v0.w, acc[1][3]);
            acc[1][4] = fmaf(w1, v1.x, acc[1][4]);
            acc[1][5] = fmaf(w1, v1.y, acc[1][5]);
            acc[1][6] = fmaf(w1, v1.z, acc[1][6]);
            acc[1][7] = fmaf(w1, v1.w, acc[1][7]);
            acc[2][0] = fmaf(w2, v0.x, acc[2][0]);
            acc[2][1] = fmaf(w2, v0.y, acc[2][1]);
            acc[2][2] = fmaf(w2, v0.z, acc[2][2]);
            acc[2][3] = fmaf(w2, v0.w, acc[2][3]);
            acc[2][4] = fmaf(w2, v1.x, acc[2][4]);
            acc[2][5] = fmaf(w2, v1.y, acc[2][5]);
            acc[2][6] = fmaf(w2, v1.z, acc[2][6]);
            acc[2][7] = fmaf(w2, v1.w, acc[2][7]);
            acc[3][0] = fmaf(w3, v0.x, acc[3][0]);
            acc[3][1] = fmaf(w3, v0.y, acc[3][1]);
            acc[3][2] = fmaf(w3, v0.z, acc[3][2]);
            acc[3][3] = fmaf(w3, v0.w, acc[3][3]);
            acc[3][4] = fmaf(w3, v1.x, acc[3][4]);
            acc[3][5] = fmaf(w3, v1.y, acc[3][5]);
            acc[3][6] = fmaf(w3, v1.z, acc[3][6]);
            acc[3][7] = fmaf(w3, v1.w, acc[3][7]);
        }
    }

    // ---- epilogue: divide by denominator, LayerNorm, ELU, store ----
    float dens[4];
    dens[0] = __shfl_sync(0xffffffffu, den, hacc);
    dens[1] = __shfl_sync(0xffffffffu, den, 8 + hacc);
    dens[2] = __shfl_sync(0xffffffffu, den, 16 + hacc);
    dens[3] = __shfl_sync(0xffffffffu, den, 24 + hacc);

#pragma unroll
    for (int rr = 0; rr < 4; rr++) {
        float inv = 1.0f / dens[rr];
        float v[8];
        float s = 0.f, q = 0.f;
#pragma unroll
        for (int k = 0; k < 8; k++) {
            v[k] = acc[rr][k] * inv;
            s += v[k];
            q = fmaf(v[k], v[k], q);
        }
#pragma unroll
        for (int off = 16; off; off >>= 1) {
            s += __shfl_xor_sync(0xffffffffu, s, off);
            q += __shfl_xor_sync(0xffffffffu, q, off);
        }
        float mu  = s * (1.0f / 256.0f);
        float var = q * (1.0f / 256.0f) - mu * mu;
        float rstd = rsqrtf(var + 1e-5f);
        float o[8];
#pragma unroll
        for (int k = 0; k < 8; k++) {
            int d = lane * 8 + k;
            float y = (v[k] - mu) * rstd * gs[d] + bs[d];
            o[k] = (y > 0.f) ? y : (__expf(y) - 1.0f);
        }
        int row = iBase + warp * 4 + rr;
        float4* op = (float4*)(out + ((size_t)b * N_ + row) * 256);
        op[lane * 2]     = make_float4(o[0], o[1], o[2], o[3]);
        op[lane * 2 + 1] = make_float4(o[4], o[5], o[6], o[7]);
    }
}

// ---------------------------------------------------------------------------
extern "C" void kernel_launch(void* const* d_in, const int* in_sizes, int n_in,
                              void* d_out, int out_size) {
    const float* x     = (const float*)d_in[0];
    const int*   adj   = (const int*)d_in[1];
    const int*   et    = (const int*)d_in[2];
    const float* W     = (const float*)d_in[3];
    const float* a1    = (const float*)d_in[4];
    const float* a2    = (const float*)d_in[5];
    const float* eemb  = (const float*)d_in[6];
    const float* gamma = (const float*)d_in[7];
    const float* beta  = (const float*)d_in[8];
    float* out = (float*)d_out;

    // K1: pack adjacency + edge types
    {
        int total4 = B_ * N_ * N_ / 4;
        pack_kernel<<<(total4 + 255) / 256, 256>>>(adj, et);
    }
    // K2: Wh = x @ W
    {
        dim3 grid(OUTF_ / 128, (B_ * N_) / 128);
        gemm_kernel<<<grid, 256>>>(x, W);
    }
    // K3: per-node per-head attention scalars
    score_kernel<<<(B_ * N_) / 8, 256>>>(a1, a2);
    // K4: fused attention + LN + ELU
    {
        size_t smem = (size_t)(4096 + 512 + 256 + 256 + CJ * 256) * sizeof(float) + 64 * CJ;
        static const size_t kSmem = smem;  // constant, deterministic
        cudaFuncSetAttribute(attn_kernel, cudaFuncAttributeMaxDynamicSharedMemorySize,
                             (int)kSmem);
        dim3 grid(N_ / 64, B_);
        attn_kernel<<<grid, 512, smem>>>(eemb, gamma, beta, out);
    }
}

// round 2
// speedup vs baseline: 1.6613x; 1.6613x over previous
#include <cuda_runtime.h>
#include <cstdint>

#define B_    16
#define N_    512
#define INF_  256
#define OUTF_ 256
#define H_    8
#define NET_  50
#define LOG2E 1.4426950408889634f
#define IT_   32      // i-rows per block
#define CJ_   64      // j-chunk

// Scratch (allocation-free rule: __device__ globals)
__device__ float g_Wh[B_ * N_ * OUTF_];          // 8 MB
__device__ float g_s1[B_ * N_ * H_];             // pre-scaled by log2e
__device__ float g_s2[B_ * N_ * H_];

// ---------------------------------------------------------------------------
// exp2(y), y pre-scaled by log2e. FMA/ALU only. Lower clamp handles mask path.
// ---------------------------------------------------------------------------
__device__ __forceinline__ float fast_exp2(float y) {
    y = fmaxf(y, -126.0f);
    float z  = y + 12582912.0f;        // 1.5*2^23 : round-to-nearest int
    float kf = z - 12582912.0f;
    float f  = y - kf;                 // f in [-0.5, 0.5]
    float p  = 1.3333558146e-3f;
    p = fmaf(p, f, 9.6181291918e-3f);
    p = fmaf(p, f, 5.5504108664e-2f);
    p = fmaf(p, f, 2.4022650696e-1f);
    p = fmaf(p, f, 6.9314718056e-1f);
    p = fmaf(p, f, 1.0f);
    int ib = __float_as_int(p) + (__float_as_int(z) << 23);
    return __int_as_float(ib);
}

__device__ __forceinline__ unsigned int f2tf32(float f) {
    unsigned int u;
    asm("cvt.rna.tf32.f32 %0, %1;" : "=r"(u) : "f"(f));
    return u;
}

// ---------------------------------------------------------------------------
// K1: Wh = x @ W   (M=8192, N=256, K=256)  fp32 tiled GEMM 128x128x16
// ---------------------------------------------------------------------------
__global__ __launch_bounds__(256) void gemm_kernel(const float* __restrict__ A,
                                                   const float* __restrict__ Bw) {
    const int K = INF_, NC = OUTF_;
    __shared__ float As[16][128];
    __shared__ float Bs[16][128];
    const int m0 = blockIdx.y * 128;
    const int n0 = blockIdx.x * 128;
    const int tid = threadIdx.x;
    const int tx = tid & 15, ty = tid >> 4;
    float acc[8][8];
#pragma unroll
    for (int i = 0; i < 8; i++)
#pragma unroll
        for (int j = 0; j < 8; j++) acc[i][j] = 0.f;

    for (int k0 = 0; k0 < K; k0 += 16) {
#pragma unroll
        for (int it = 0; it < 2; it++) {
            int idx = tid + it * 256;
            int row = idx >> 2, c4 = idx & 3;
            float4 v = ((const float4*)A)[(size_t)(m0 + row) * (K / 4) + (k0 >> 2) + c4];
            As[c4 * 4 + 0][row] = v.x;
            As[c4 * 4 + 1][row] = v.y;
            As[c4 * 4 + 2][row] = v.z;
            As[c4 * 4 + 3][row] = v.w;
        }
#pragma unroll
        for (int it = 0; it < 2; it++) {
            int idx = tid + it * 256;
            int row = idx >> 5, c4 = idx & 31;
            ((float4*)&Bs[row][0])[c4] =
                ((const float4*)Bw)[(size_t)(k0 + row) * (NC / 4) + (n0 >> 2) + c4];
        }
        __syncthreads();
#pragma unroll
        for (int k = 0; k < 16; k++) {
            float ra[8], rb[8];
            *(float4*)&ra[0] = *(float4*)&As[k][ty * 8];
            *(float4*)&ra[4] = *(float4*)&As[k][ty * 8 + 4];
            *(float4*)&rb[0] = *(float4*)&Bs[k][tx * 8];
            *(float4*)&rb[4] = *(float4*)&Bs[k][tx * 8 + 4];
#pragma unroll
            for (int i = 0; i < 8; i++)
#pragma unroll
                for (int j = 0; j < 8; j++) acc[i][j] = fmaf(ra[i], rb[j], acc[i][j]);
        }
        __syncthreads();
    }
#pragma unroll
    for (int i = 0; i < 8; i++) {
        int row = m0 + ty * 8 + i;
#pragma unroll
        for (int j4 = 0; j4 < 2; j4++) {
            float4 v = make_float4(acc[i][j4 * 4], acc[i][j4 * 4 + 1],
                                   acc[i][j4 * 4 + 2], acc[i][j4 * 4 + 3]);
            ((float4*)g_Wh)[(size_t)row * (NC / 4) + (n0 >> 2) + tx * 2 + j4] = v;
        }
    }
}

// ---------------------------------------------------------------------------
// K2: s1[row,h] = (Wh[row,h,:] . a1) * log2e ; same for s2. One warp per row.
// ---------------------------------------------------------------------------
__global__ __launch_bounds__(256) void score_kernel(const float* __restrict__ a1,
                                                    const float* __restrict__ a2) {
    __shared__ float a1s[32], a2s[32];
    int tid = threadIdx.x;
    if (tid < 32) { a1s[tid] = a1[tid]; a2s[tid] = a2[tid]; }
    __syncthreads();
    int warp = tid >> 5, lane = tid & 31;
    int row = blockIdx.x * 8 + warp;
    const float4* wh = (const float4*)(g_Wh + (size_t)row * 256);
    float4 v0 = wh[lane * 2];
    float4 v1 = wh[lane * 2 + 1];
    int d0 = (lane * 8) & 31;  // offset within head
    float p1 = v0.x * a1s[d0] + v0.y * a1s[d0 + 1] + v0.z * a1s[d0 + 2] + v0.w * a1s[d0 + 3] +
               v1.x * a1s[d0 + 4] + v1.y * a1s[d0 + 5] + v1.z * a1s[d0 + 6] + v1.w * a1s[d0 + 7];
    float p2 = v0.x * a2s[d0] + v0.y * a2s[d0 + 1] + v0.z * a2s[d0 + 2] + v0.w * a2s[d0 + 3] +
               v1.x * a2s[d0 + 4] + v1.y * a2s[d0 + 5] + v1.z * a2s[d0 + 6] + v1.w * a2s[d0 + 7];
    p1 += __shfl_xor_sync(0xffffffffu, p1, 1);
    p1 += __shfl_xor_sync(0xffffffffu, p1, 2);
    p2 += __shfl_xor_sync(0xffffffffu, p2, 1);
    p2 += __shfl_xor_sync(0xffffffffu, p2, 2);
    if ((lane & 3) == 0) {
        int h = lane >> 2;
        g_s1[(size_t)row * 8 + h] = p1 * LOG2E;
        g_s2[(size_t)row * 8 + h] = p2 * LOG2E;
    }
}

// ---------------------------------------------------------------------------
// K3: fused attention via mma.sync tf32 + softmax + LayerNorm + ELU
// Block: 512 thr / 16 warps; 32 i-rows per block; warp = (i16-tile, head).
// A-fragment (softmax weights) computed in registers; B = Wh (tf32 in SMEM).
// SMEM layout (float units):
//   [0]     s2s    4096      (whole-batch s2, pre-scaled)
//   [4096]  embT   512       (8 heads x 64; entry>=50 = -12000 mask)
//   [4608]  gs     256
//   [4864]  bs     256
//   [5120]  s1s    256       (32 rows x 8)
//   [5376]  denS   256       (32 rows x 8)
//   [5632]  codesS 544 u32   (32 rows x 17-padded words, chunk codes)
//   [6176]  WhS    16640 u32 (64 x 260-padded tf32)   -- aliased as outS f32
// total 22816 * 4B = 91264 B
// ---------------------------------------------------------------------------
__global__ void __launch_bounds__(512, 2)
attn_kernel(const int* __restrict__ adj, const int* __restrict__ et,
            const float* __restrict__ edge_emb,
            const float* __restrict__ gamma, const float* __restrict__ beta,
            float* __restrict__ out) {
    extern __shared__ float sm[];
    float* s2s  = sm;
    float* embT = sm + 4096;
    float* gs   = sm + 4608;
    float* bs   = sm + 4864;
    float* s1s  = sm + 5120;
    float* denS = sm + 5376;
    unsigned int* codesS = (unsigned int*)(sm + 5632);
    unsigned int* WhS    = (unsigned int*)(sm + 6176);
    float*        outS   = (float*)(sm + 6176);

    const int b     = blockIdx.y;
    const int iBase = blockIdx.x * IT_;
    const int tid   = threadIdx.x;
    const int warp  = tid >> 5, lane = tid & 31;

    // ---- one-time staging ----
    const float* s2g = g_s2 + (size_t)b * N_ * H_;
    for (int i = tid; i < N_ * H_; i += 512) s2s[i] = s2g[i];
    {
        int h = tid >> 6, e = tid & 63;
        embT[tid] = (e < NET_) ? edge_emb[e * H_ + h] * LOG2E : -12000.0f;
    }
    if (tid < 256) { gs[tid] = gamma[tid]; bs[tid] = beta[tid]; }
    if (tid < IT_ * H_) s1s[tid] = g_s1[((size_t)b * N_ + iBase) * H_ + tid];

    // task assignment: warp -> (i16 tile, head)
    const int it = warp >> 3;       // 0..1
    const int h  = warp & 7;        // head
    const int g  = lane >> 2;       // groupID 0..7
    const int t  = lane & 3;        // threadInGroup 0..3
    const int r0 = it * 16 + g;     // local row (0..15 of tile half 1)
    const int r1 = r0 + 8;
    const int sh = t * 8;           // byte shift for code extraction
    const float* embH = embT + h * 64;

    __syncthreads();
    const float s1a = s1s[r0 * 8 + h];
    const float s1b = s1s[r1 * 8 + h];

    float acc[4][4];                // 4 n8-fragments (n=32), c0..c3 each
#pragma unroll
    for (int nf = 0; nf < 4; nf++)
#pragma unroll
        for (int k = 0; k < 4; k++) acc[nf][k] = 0.f;
    float den0 = 0.f, den1 = 0.f;

    const int4* adjRow = (const int4*)(adj + ((size_t)(b * N_ + iBase)) * N_);
    const int4* etRow  = (const int4*)(et  + ((size_t)(b * N_ + iBase)) * N_);

    for (int jc = 0; jc < N_; jc += CJ_) {
        __syncthreads();
        // stage Wh chunk [64 j][256 d] -> tf32, padded rows of 260
        const float4* whg = (const float4*)(g_Wh + ((size_t)b * N_ + jc) * 256);
        for (int idx = tid; idx < 64 * 64; idx += 512) {
            int rr = idx >> 6, cc = idx & 63;
            float4 v = whg[idx];
            uint4 u;
            u.x = f2tf32(v.x); u.y = f2tf32(v.y); u.z = f2tf32(v.z); u.w = f2tf32(v.w);
            *(uint4*)&WhS[rr * 260 + cc * 4] = u;
        }
        // stage+pack codes chunk [32 i][64 j] -> u32 words, padded rows of 17
        {
            int rr = tid >> 4, ww = tid & 15;   // 32 x 16
            int4 a4 = adjRow[rr * (N_ / 4) + (jc >> 2) + ww];
            int4 t4 = etRow[rr * (N_ / 4) + (jc >> 2) + ww];
            unsigned int c0 = a4.x ? (unsigned int)t4.x : 50u;
            unsigned int c1 = a4.y ? (unsigned int)t4.y : 50u;
            unsigned int c2 = a4.z ? (unsigned int)t4.z : 50u;
            unsigned int c3 = a4.w ? (unsigned int)t4.w : 50u;
            codesS[rr * 17 + ww] = c0 | (c1 << 8) | (c2 << 16) | (c3 << 24);
        }
        __syncthreads();

        const unsigned int* cR0 = codesS + r0 * 17;
        const unsigned int* cR1 = codesS + r1 * 17;
#pragma unroll
        for (int k8 = 0; k8 < 8; k8++) {
            const int jl  = k8 * 8;           // chunk-local j base
            const int jgl = jc + jl;          // global j base
            unsigned int cw00 = cR0[k8 * 2];      // row r0, cols jl..jl+3
            unsigned int cw01 = cR0[k8 * 2 + 1];  // row r0, cols jl+4..jl+7
            unsigned int cw10 = cR1[k8 * 2];
            unsigned int cw11 = cR1[k8 * 2 + 1];

            float s2c0 = s2s[(jgl + t) * 8 + h];
            float s2c1 = s2s[(jgl + t + 4) * 8 + h];

            float e00 = s1a + s2c0 + embH[(cw00 >> sh) & 0xff];  // (r0, c)
            float e10 = s1b + s2c0 + embH[(cw10 >> sh) & 0xff];  // (r1, c)
            float e01 = s1a + s2c1 + embH[(cw01 >> sh) & 0xff];  // (r0, c+4)
            float e11 = s1b + s2c1 + embH[(cw11 >> sh) & 0xff];  // (r1, c+4)
            e00 = fmaxf(e00, 0.2f * e00);
            e10 = fmaxf(e10, 0.2f * e10);
            e01 = fmaxf(e01, 0.2f * e01);
            e11 = fmaxf(e11, 0.2f * e11);
            float w00 = fast_exp2(e00);
            float w10 = fast_exp2(e10);
            float w01 = fast_exp2(e01);
            float w11 = fast_exp2(e11);
            den0 += w00 + w01;
            den1 += w10 + w11;

            unsigned int a0 = f2tf32(w00);  // (r0, c)
            unsigned int a1 = f2tf32(w10);  // (r1, c)
            unsigned int a2 = f2tf32(w01);  // (r0, c+4)
            unsigned int a3 = f2tf32(w11);  // (r1, c+4)

            const unsigned int* B0 = WhS + (jl + t) * 260 + h * 32;      // k row t
            const unsigned int* B1 = WhS + (jl + t + 4) * 260 + h * 32;  // k row t+4
#pragma unroll
            for (int nf = 0; nf < 4; nf++) {
                unsigned int b0 = B0[nf * 8 + g];
                unsigned int b1 = B1[nf * 8 + g];
                asm volatile(
                    "mma.sync.aligned.m16n8k8.row.col.f32.tf32.tf32.f32 "
                    "{%0,%1,%2,%3}, {%4,%5,%6,%7}, {%8,%9}, {%0,%1,%2,%3};"
                    : "+f"(acc[nf][0]), "+f"(acc[nf][1]), "+f"(acc[nf][2]), "+f"(acc[nf][3])
                    : "r"(a0), "r"(a1), "r"(a2), "r"(a3), "r"(b0), "r"(b1));
            }
        }
    }

    // quad-reduce denominators (lanes 4g..4g+3 share rows r0/r1)
    den0 += __shfl_xor_sync(0xffffffffu, den0, 1);
    den0 += __shfl_xor_sync(0xffffffffu, den0, 2);
    den1 += __shfl_xor_sync(0xffffffffu, den1, 1);
    den1 += __shfl_xor_sync(0xffffffffu, den1, 2);

    __syncthreads();  // all MMA reads of WhS done; safe to alias as outS
    if (t == 0) {
        denS[r0 * 8 + h] = den0;
        denS[r1 * 8 + h] = den1;
    }
#pragma unroll
    for (int nf = 0; nf < 4; nf++) {
        int col = h * 32 + nf * 8 + t * 2;
        *(float2*)&outS[r0 * 260 + col] = make_float2(acc[nf][0], acc[nf][1]);
        *(float2*)&outS[r1 * 260 + col] = make_float2(acc[nf][2], acc[nf][3]);
    }
    __syncthreads();

    // ---- LayerNorm + ELU: 2 rows per warp, lane covers dims [8*lane, 8*lane+8)
#pragma unroll
    for (int rr = warp * 2; rr < warp * 2 + 2; rr++) {
        float inv = 1.0f / denS[rr * 8 + (lane >> 2)];
        float4 v0 = *(float4*)&outS[rr * 260 + lane * 8];
        float4 v1 = *(float4*)&outS[rr * 260 + lane * 8 + 4];
        float v[8] = {v0.x, v0.y, v0.z, v0.w, v1.x, v1.y, v1.z, v1.w};
        float s = 0.f, q = 0.f;
#pragma unroll
        for (int k = 0; k < 8; k++) {
            v[k] *= inv;
            s += v[k];
            q = fmaf(v[k], v[k], q);
        }
#pragma unroll
        for (int off = 16; off; off >>= 1) {
            s += __shfl_xor_sync(0xffffffffu, s, off);
            q += __shfl_xor_sync(0xffffffffu, q, off);
        }
        float mu   = s * (1.0f / 256.0f);
        float var  = q * (1.0f / 256.0f) - mu * mu;
        float rstd = rsqrtf(var + 1e-5f);
        float o[8];
#pragma unroll
        for (int k = 0; k < 8; k++) {
            int d = lane * 8 + k;
            float y = (v[k] - mu) * rstd * gs[d] + bs[d];
            o[k] = (y > 0.f) ? y : (__expf(y) - 1.0f);
        }
        float4* op = (float4*)(out + ((size_t)b * N_ + iBase + rr) * 256);
        op[lane * 2]     = make_float4(o[0], o[1], o[2], o[3]);
        op[lane * 2 + 1] = make_float4(o[4], o[5], o[6], o[7]);
    }
}

// ---------------------------------------------------------------------------
extern "C" void kernel_launch(void* const* d_in, const int* in_sizes, int n_in,
                              void* d_out, int out_size) {
    const float* x     = (const float*)d_in[0];
    const int*   adj   = (const int*)d_in[1];
    const int*   et    = (const int*)d_in[2];
    const float* W     = (const float*)d_in[3];
    const float* a1    = (const float*)d_in[4];
    const float* a2    = (const float*)d_in[5];
    const float* eemb  = (const float*)d_in[6];
    const float* gamma = (const float*)d_in[7];
    const float* beta  = (const float*)d_in[8];
    float* out = (float*)d_out;

    // K1: Wh = x @ W
    {
        dim3 grid(OUTF_ / 128, (B_ * N_) / 128);
        gemm_kernel<<<grid, 256>>>(x, W);
    }
    // K2: per-node per-head attention scalars
    score_kernel<<<(B_ * N_) / 8, 256>>>(a1, a2);
    // K3: fused attention (tensor cores) + LN + ELU
    {
        const int smemBytes = 22816 * 4;  // 91264
        cudaFuncSetAttribute(attn_kernel, cudaFuncAttributeMaxDynamicSharedMemorySize,
                             smemBytes);
        dim3 grid(N_ / IT_, B_);
        attn_kernel<<<grid, 512, smemBytes>>>(adj, et, eemb, gamma, beta, out);
    }
}

// round 3
// speedup vs baseline: 1.8768x; 1.1297x over previous
#include <cuda_runtime.h>
#include <cstdint>

#define B_    16
#define N_    512
#define INF_  256
#define OUTF_ 256
#define H_    8
#define NET_  50
#define LOG2E 1.4426950408889634f
#define IT_   32      // i-rows per block (attn)
#define CJ_   64      // j-chunk (attn)

// Scratch (allocation-free rule: __device__ globals)
__device__ float g_Wh[B_ * N_ * OUTF_];   // tf32-valued floats, 8 MB
__device__ float g_s1[B_ * N_ * H_];      // pre-scaled by log2e (fp32-exact)
__device__ float g_s2[B_ * N_ * H_];

// ---------------------------------------------------------------------------
__device__ __forceinline__ float fast_exp2(float y) {
    y = fmaxf(y, -126.0f);
    float z  = y + 12582912.0f;        // 1.5*2^23 : round-to-nearest int
    float kf = z - 12582912.0f;
    float f  = y - kf;                 // f in [-0.5, 0.5]
    float p  = 1.3333558146e-3f;
    p = fmaf(p, f, 9.6181291918e-3f);
    p = fmaf(p, f, 5.5504108664e-2f);
    p = fmaf(p, f, 2.4022650696e-1f);
    p = fmaf(p, f, 6.9314718056e-1f);
    p = fmaf(p, f, 1.0f);
    int ib = __float_as_int(p) + (__float_as_int(z) << 23);
    return __int_as_float(ib);
}

__device__ __forceinline__ float tf32f(float f) {
    unsigned int u;
    asm("cvt.rna.tf32.f32 %0, %1;" : "=r"(u) : "f"(f));
    return __uint_as_float(u);
}

__device__ __forceinline__ void mma_tf32(float acc[4], float a0, float a1f,
                                         float a2f, float a3f, float b0, float b1) {
    asm volatile(
        "mma.sync.aligned.m16n8k8.row.col.f32.tf32.tf32.f32 "
        "{%0,%1,%2,%3}, {%4,%5,%6,%7}, {%8,%9}, {%0,%1,%2,%3};"
        : "+f"(acc[0]), "+f"(acc[1]), "+f"(acc[2]), "+f"(acc[3])
        : "r"(__float_as_uint(a0)), "r"(__float_as_uint(a1f)),
          "r"(__float_as_uint(a2f)), "r"(__float_as_uint(a3f)),
          "r"(__float_as_uint(b0)), "r"(__float_as_uint(b1)));
}

// ---------------------------------------------------------------------------
// K1: Wh = x @ W via 3xTF32 tensor-core GEMM (error ~fp32), fused epilogue:
//   - s1/s2 = (Wh . a1/a2) * log2e computed from fp32 accumulators
//   - g_Wh stored pre-converted to tf32 bit patterns (attn consumes raw)
// Block 256 thr / 8 warps (4 M x 2 N), tile 128x128, k-chunk 16.
// ---------------------------------------------------------------------------
#define ASTR 20
#define BSTR 136
__global__ __launch_bounds__(256) void gemm_score_kernel(
    const float* __restrict__ A, const float* __restrict__ Bw,
    const float* __restrict__ a1, const float* __restrict__ a2) {
    __shared__ float Ahi[128 * ASTR], Alo[128 * ASTR];
    __shared__ float Bhi[16 * BSTR], Blo[16 * BSTR];
    __shared__ float a1s[32], a2s[32];

    const int tid = threadIdx.x;
    const int m0 = blockIdx.y * 128;
    const int n0 = blockIdx.x * 128;
    if (tid < 32) { a1s[tid] = a1[tid]; a2s[tid] = a2[tid]; }

    const int warp = tid >> 5, lane = tid & 31;
    const int wm = warp >> 1, wn = warp & 1;
    const int g = lane >> 2, t = lane & 3;

    float acc[2][8][4];
#pragma unroll
    for (int mt = 0; mt < 2; mt++)
#pragma unroll
        for (int nf = 0; nf < 8; nf++)
#pragma unroll
            for (int c = 0; c < 4; c++) acc[mt][nf][c] = 0.f;

    for (int k0 = 0; k0 < INF_; k0 += 16) {
        float4 va[2], vb[2];
#pragma unroll
        for (int it = 0; it < 2; it++) {
            int idx = tid + it * 256;
            va[it] = ((const float4*)A)[(size_t)(m0 + (idx >> 2)) * 64 + (k0 >> 2) + (idx & 3)];
            vb[it] = ((const float4*)Bw)[(size_t)(k0 + (idx >> 5)) * 64 + (n0 >> 2) + (idx & 31)];
        }
        __syncthreads();
#pragma unroll
        for (int it = 0; it < 2; it++) {
            int idx = tid + it * 256;
            float4 v = va[it];
            float4 hi, lo;
            hi.x = tf32f(v.x); lo.x = tf32f(v.x - hi.x);
            hi.y = tf32f(v.y); lo.y = tf32f(v.y - hi.y);
            hi.z = tf32f(v.z); lo.z = tf32f(v.z - hi.z);
            hi.w = tf32f(v.w); lo.w = tf32f(v.w - hi.w);
            int off = (idx >> 2) * ASTR + (idx & 3) * 4;
            *(float4*)&Ahi[off] = hi;
            *(float4*)&Alo[off] = lo;
            v = vb[it];
            hi.x = tf32f(v.x); lo.x = tf32f(v.x - hi.x);
            hi.y = tf32f(v.y); lo.y = tf32f(v.y - hi.y);
            hi.z = tf32f(v.z); lo.z = tf32f(v.z - hi.z);
            hi.w = tf32f(v.w); lo.w = tf32f(v.w - hi.w);
            off = (idx >> 5) * BSTR + (idx & 31) * 4;
            *(float4*)&Bhi[off] = hi;
            *(float4*)&Blo[off] = lo;
        }
        __syncthreads();
#pragma unroll
        for (int k8 = 0; k8 < 2; k8++) {
            const int kk = k8 * 8 + t;
            float ah[2][4], al[2][4];
#pragma unroll
            for (int mt = 0; mt < 2; mt++) {
                int r = (wm * 32 + mt * 16 + g) * ASTR;
                ah[mt][0] = Ahi[r + kk];
                ah[mt][1] = Ahi[r + 8 * ASTR + kk];
                ah[mt][2] = Ahi[r + kk + 4];
                ah[mt][3] = Ahi[r + 8 * ASTR + kk + 4];
                al[mt][0] = Alo[r + kk];
                al[mt][1] = Alo[r + 8 * ASTR + kk];
                al[mt][2] = Alo[r + kk + 4];
                al[mt][3] = Alo[r + 8 * ASTR + kk + 4];
            }
#pragma unroll
            for (int nf = 0; nf < 8; nf++) {
                int c = wn * 64 + nf * 8 + g;
                float bh0 = Bhi[kk * BSTR + c];
                float bh1 = Bhi[(kk + 4) * BSTR + c];
                float bl0 = Blo[kk * BSTR + c];
                float bl1 = Blo[(kk + 4) * BSTR + c];
#pragma unroll
                for (int mt = 0; mt < 2; mt++) {
                    mma_tf32(acc[mt][nf], ah[mt][0], ah[mt][1], ah[mt][2], ah[mt][3], bh0, bh1);
                    mma_tf32(acc[mt][nf], ah[mt][0], ah[mt][1], ah[mt][2], ah[mt][3], bl0, bl1);
                    mma_tf32(acc[mt][nf], al[mt][0], al[mt][1], al[mt][2], al[mt][3], bh0, bh1);
                }
            }
        }
    }

    // ---- epilogue: scores (fp32) + tf32 Wh store ----
    const int hb = (n0 >> 5) + wn * 2;
#pragma unroll
    for (int mt = 0; mt < 2; mt++) {
        float pA1[2] = {0.f, 0.f}, pA2[2] = {0.f, 0.f};
        float pB1[2] = {0.f, 0.f}, pB2[2] = {0.f, 0.f};
#pragma unroll
        for (int nf = 0; nf < 8; nf++) {
            int d0 = (nf * 8 + t * 2) & 31;
            int hh = nf >> 2;
            float c0 = acc[mt][nf][0], c1 = acc[mt][nf][1];
            float c2 = acc[mt][nf][2], c3 = acc[mt][nf][3];
            pA1[hh] += c0 * a1s[d0] + c1 * a1s[d0 + 1];
            pA2[hh] += c0 * a2s[d0] + c1 * a2s[d0 + 1];
            pB1[hh] += c2 * a1s[d0] + c3 * a1s[d0 + 1];
            pB2[hh] += c2 * a2s[d0] + c3 * a2s[d0 + 1];
        }
#pragma unroll
        for (int hh = 0; hh < 2; hh++) {
            pA1[hh] += __shfl_xor_sync(0xffffffffu, pA1[hh], 1);
            pA1[hh] += __shfl_xor_sync(0xffffffffu, pA1[hh], 2);
            pA2[hh] += __shfl_xor_sync(0xffffffffu, pA2[hh], 1);
            pA2[hh] += __shfl_xor_sync(0xffffffffu, pA2[hh], 2);
            pB1[hh] += __shfl_xor_sync(0xffffffffu, pB1[hh], 1);
            pB1[hh] += __shfl_xor_sync(0xffffffffu, pB1[hh], 2);
            pB2[hh] += __shfl_xor_sync(0xffffffffu, pB2[hh], 1);
            pB2[hh] += __shfl_xor_sync(0xffffffffu, pB2[hh], 2);
        }
        int rA = m0 + wm * 32 + mt * 16 + g;
        int rB = rA + 8;
        if (t == 0) {
            g_s1[(size_t)rA * 8 + hb]     = pA1[0] * LOG2E;
            g_s1[(size_t)rA * 8 + hb + 1] = pA1[1] * LOG2E;
            g_s2[(size_t)rA * 8 + hb]     = pA2[0] * LOG2E;
            g_s2[(size_t)rA * 8 + hb + 1] = pA2[1] * LOG2E;
            g_s1[(size_t)rB * 8 + hb]     = pB1[0] * LOG2E;
            g_s1[(size_t)rB * 8 + hb + 1] = pB1[1] * LOG2E;
            g_s2[(size_t)rB * 8 + hb]     = pB2[0] * LOG2E;
            g_s2[(size_t)rB * 8 + hb + 1] = pB2[1] * LOG2E;
        }
#pragma unroll
        for (int nf = 0; nf < 8; nf++) {
            int col = n0 + wn * 64 + nf * 8 + t * 2;
            *(float2*)&g_Wh[(size_t)rA * 256 + col] =
                make_float2(tf32f(acc[mt][nf][0]), tf32f(acc[mt][nf][1]));
            *(float2*)&g_Wh[(size_t)rB * 256 + col] =
                make_float2(tf32f(acc[mt][nf][2]), tf32f(acc[mt][nf][3]));
        }
    }
}

// ---------------------------------------------------------------------------
// K2: fused attention via mma.sync tf32 + softmax + LayerNorm + ELU
// (unchanged from round 2 except: Wh already tf32 -> raw u32 staging)
// ---------------------------------------------------------------------------
__global__ void __launch_bounds__(512, 2)
attn_kernel(const int* __restrict__ adj, const int* __restrict__ et,
            const float* __restrict__ edge_emb,
            const float* __restrict__ gamma, const float* __restrict__ beta,
            float* __restrict__ out) {
    extern __shared__ float sm[];
    float* s2s  = sm;
    float* embT = sm + 4096;
    float* gs   = sm + 4608;
    float* bs   = sm + 4864;
    float* s1s  = sm + 5120;
    float* denS = sm + 5376;
    unsigned int* codesS = (unsigned int*)(sm + 5632);
    unsigned int* WhS    = (unsigned int*)(sm + 6176);
    float*        outS   = (float*)(sm + 6176);

    const int b     = blockIdx.y;
    const int iBase = blockIdx.x * IT_;
    const int tid   = threadIdx.x;
    const int warp  = tid >> 5, lane = tid & 31;

    const float* s2g = g_s2 + (size_t)b * N_ * H_;
    for (int i = tid; i < N_ * H_; i += 512) s2s[i] = s2g[i];
    {
        int h = tid >> 6, e = tid & 63;
        embT[tid] = (e < NET_) ? edge_emb[e * H_ + h] * LOG2E : -12000.0f;
    }
    if (tid < 256) { gs[tid] = gamma[tid]; bs[tid] = beta[tid]; }
    if (tid < IT_ * H_) s1s[tid] = g_s1[((size_t)b * N_ + iBase) * H_ + tid];

    const int it = warp >> 3;
    const int h  = warp & 7;
    const int g  = lane >> 2;
    const int t  = lane & 3;
    const int r0 = it * 16 + g;
    const int r1 = r0 + 8;
    const int sh = t * 8;
    const float* embH = embT + h * 64;

    __syncthreads();
    const float s1a = s1s[r0 * 8 + h];
    const float s1b = s1s[r1 * 8 + h];

    float acc[4][4];
#pragma unroll
    for (int nf = 0; nf < 4; nf++)
#pragma unroll
        for (int k = 0; k < 4; k++) acc[nf][k] = 0.f;
    float den0 = 0.f, den1 = 0.f;

    const int4* adjRow = (const int4*)(adj + ((size_t)(b * N_ + iBase)) * N_);
    const int4* etRow  = (const int4*)(et  + ((size_t)(b * N_ + iBase)) * N_);

    for (int jc = 0; jc < N_; jc += CJ_) {
        __syncthreads();
        const uint4* whg = (const uint4*)(g_Wh + ((size_t)b * N_ + jc) * 256);
        for (int idx = tid; idx < 64 * 64; idx += 512) {
            int rr = idx >> 6, cc = idx & 63;
            *(uint4*)&WhS[rr * 260 + cc * 4] = whg[idx];
        }
        {
            int rr = tid >> 4, ww = tid & 15;
            int4 a4 = adjRow[rr * (N_ / 4) + (jc >> 2) + ww];
            int4 t4 = etRow[rr * (N_ / 4) + (jc >> 2) + ww];
            unsigned int c0 = a4.x ? (unsigned int)t4.x : 50u;
            unsigned int c1 = a4.y ? (unsigned int)t4.y : 50u;
            unsigned int c2 = a4.z ? (unsigned int)t4.z : 50u;
            unsigned int c3 = a4.w ? (unsigned int)t4.w : 50u;
            codesS[rr * 17 + ww] = c0 | (c1 << 8) | (c2 << 16) | (c3 << 24);
        }
        __syncthreads();

        const unsigned int* cR0 = codesS + r0 * 17;
        const unsigned int* cR1 = codesS + r1 * 17;
#pragma unroll
        for (int k8 = 0; k8 < 8; k8++) {
            const int jl  = k8 * 8;
            const int jgl = jc + jl;
            unsigned int cw00 = cR0[k8 * 2];
            unsigned int cw01 = cR0[k8 * 2 + 1];
            unsigned int cw10 = cR1[k8 * 2];
            unsigned int cw11 = cR1[k8 * 2 + 1];

            float s2c0 = s2s[(jgl + t) * 8 + h];
            float s2c1 = s2s[(jgl + t + 4) * 8 + h];

            float e00 = s1a + s2c0 + embH[(cw00 >> sh) & 0xff];
            float e10 = s1b + s2c0 + embH[(cw10 >> sh) & 0xff];
            float e01 = s1a + s2c1 + embH[(cw01 >> sh) & 0xff];
            float e11 = s1b + s2c1 + embH[(cw11 >> sh) & 0xff];
            e00 = fmaxf(e00, 0.2f * e00);
            e10 = fmaxf(e10, 0.2f * e10);
            e01 = fmaxf(e01, 0.2f * e01);
            e11 = fmaxf(e11, 0.2f * e11);
            float w00 = fast_exp2(e00);
            float w10 = fast_exp2(e10);
            float w01 = fast_exp2(e01);
            float w11 = fast_exp2(e11);
            den0 += w00 + w01;
            den1 += w10 + w11;

            const unsigned int* B0 = WhS + (jl + t) * 260 + h * 32;
            const unsigned int* B1 = WhS + (jl + t + 4) * 260 + h * 32;
#pragma unroll
            for (int nf = 0; nf < 4; nf++) {
                unsigned int b0 = B0[nf * 8 + g];
                unsigned int b1 = B1[nf * 8 + g];
                asm volatile(
                    "mma.sync.aligned.m16n8k8.row.col.f32.tf32.tf32.f32 "
                    "{%0,%1,%2,%3}, {%4,%5,%6,%7}, {%8,%9}, {%0,%1,%2,%3};"
                    : "+f"(acc[nf][0]), "+f"(acc[nf][1]), "+f"(acc[nf][2]), "+f"(acc[nf][3])
                    : "r"(__float_as_uint(tf32f(w00))), "r"(__float_as_uint(tf32f(w10))),
                      "r"(__float_as_uint(tf32f(w01))), "r"(__float_as_uint(tf32f(w11))),
                      "r"(b0), "r"(b1));
            }
        }
    }

    den0 += __shfl_xor_sync(0xffffffffu, den0, 1);
    den0 += __shfl_xor_sync(0xffffffffu, den0, 2);
    den1 += __shfl_xor_sync(0xffffffffu, den1, 1);
    den1 += __shfl_xor_sync(0xffffffffu, den1, 2);

    __syncthreads();
    if (t == 0) {
        denS[r0 * 8 + h] = den0;
        denS[r1 * 8 + h] = den1;
    }
#pragma unroll
    for (int nf = 0; nf < 4; nf++) {
        int col = h * 32 + nf * 8 + t * 2;
        *(float2*)&outS[r0 * 260 + col] = make_float2(acc[nf][0], acc[nf][1]);
        *(float2*)&outS[r1 * 260 + col] = make_float2(acc[nf][2], acc[nf][3]);
    }
    __syncthreads();

#pragma unroll
    for (int rr = warp * 2; rr < warp * 2 + 2; rr++) {
        float inv = 1.0f / denS[rr * 8 + (lane >> 2)];
        float4 v0 = *(float4*)&outS[rr * 260 + lane * 8];
        float4 v1 = *(float4*)&outS[rr * 260 + lane * 8 + 4];
        float v[8] = {v0.x, v0.y, v0.z, v0.w, v1.x, v1.y, v1.z, v1.w};
        float s = 0.f, q = 0.f;
#pragma unroll
        for (int k = 0; k < 8; k++) {
            v[k] *= inv;
            s += v[k];
            q = fmaf(v[k], v[k], q);
        }
#pragma unroll
        for (int off = 16; off; off >>= 1) {
            s += __shfl_xor_sync(0xffffffffu, s, off);
            q += __shfl_xor_sync(0xffffffffu, q, off);
        }
        float mu   = s * (1.0f / 256.0f);
        float var  = q * (1.0f / 256.0f) - mu * mu;
        float rstd = rsqrtf(var + 1e-5f);
        float o[8];
#pragma unroll
        for (int k = 0; k < 8; k++) {
            int d = lane * 8 + k;
            float y = (v[k] - mu) * rstd * gs[d] + bs[d];
            o[k] = (y > 0.f) ? y : (__expf(y) - 1.0f);
        }
        float4* op = (float4*)(out + ((size_t)b * N_ + iBase + rr) * 256);
        op[lane * 2]     = make_float4(o[0], o[1], o[2], o[3]);
        op[lane * 2 + 1] = make_float4(o[4], o[5], o[6], o[7]);
    }
}

// ---------------------------------------------------------------------------
extern "C" void kernel_launch(void* const* d_in, const int* in_sizes, int n_in,
                              void* d_out, int out_size) {
    const float* x     = (const float*)d_in[0];
    const int*   adj   = (const int*)d_in[1];
    const int*   et    = (const int*)d_in[2];
    const float* W     = (const float*)d_in[3];
    const float* a1    = (const float*)d_in[4];
    const float* a2    = (const float*)d_in[5];
    const float* eemb  = (const float*)d_in[6];
    const float* gamma = (const float*)d_in[7];
    const float* beta  = (const float*)d_in[8];
    float* out = (float*)d_out;

    // K1: Wh = x @ W (3xTF32 tensor cores) + fused s1/s2 scores
    {
        dim3 grid(OUTF_ / 128, (B_ * N_) / 128);
        gemm_score_kernel<<<grid, 256>>>(x, W, a1, a2);
    }
    // K2: fused attention (tensor cores) + LN + ELU
    {
        const int smemBytes = 22816 * 4;  // 91264
        cudaFuncSetAttribute(attn_kernel, cudaFuncAttributeMaxDynamicSharedMemorySize,
                             smemBytes);
        dim3 grid(N_ / IT_, B_);
        attn_kernel<<<grid, 512, smemBytes>>>(adj, et, eemb, gamma, beta, out);
    }
}

// round 4
// speedup vs baseline: 1.9678x; 1.0485x over previous
#include <cuda_runtime.h>
#include <cstdint>

#define B_    16
#define N_    512
#define INF_  256
#define OUTF_ 256
#define H_    8
#define NET_  50
#define LOG2E 1.4426950408889634f
#define IT_   32      // i-rows per block (attn)
#define CJ_   64      // j-chunk (attn)
#define WSTR  264     // WhS row stride (floats)

// Scratch (allocation-free rule: __device__ globals)
// g_Wh layout: row-major [row][256], but within each head's 32 dims the order
// is permuted: storage pos p = g*4 + nf  <->  dim dl = nf*8 + g.
__device__ float g_Wh[B_ * N_ * OUTF_];
__device__ float g_s1[B_ * N_ * H_];      // pre-scaled by log2e (fp32-exact)
__device__ float g_s2[B_ * N_ * H_];

// ---------------------------------------------------------------------------
__device__ __forceinline__ float ex2f(float x) {   // MUFU.EX2
    float r;
    asm("ex2.approx.f32 %0, %1;" : "=f"(r) : "f"(x));
    return r;
}

__device__ __forceinline__ float tf32f(float f) {
    unsigned int u;
    asm("cvt.rna.tf32.f32 %0, %1;" : "=r"(u) : "f"(f));
    return __uint_as_float(u);
}

__device__ __forceinline__ void mma_tf32(float acc[4], float a0, float a1f,
                                         float a2f, float a3f, float b0, float b1) {
    asm volatile(
        "mma.sync.aligned.m16n8k8.row.col.f32.tf32.tf32.f32 "
        "{%0,%1,%2,%3}, {%4,%5,%6,%7}, {%8,%9}, {%0,%1,%2,%3};"
        : "+f"(acc[0]), "+f"(acc[1]), "+f"(acc[2]), "+f"(acc[3])
        : "r"(__float_as_uint(a0)), "r"(__float_as_uint(a1f)),
          "r"(__float_as_uint(a2f)), "r"(__float_as_uint(a3f)),
          "r"(__float_as_uint(b0)), "r"(__float_as_uint(b1)));
}

// ---------------------------------------------------------------------------
// K1: Wh = x @ W via 3xTF32 tensor-core GEMM + fused s1/s2 score epilogue.
// g_Wh written in the head-permuted tf32 layout consumed by attn.
// ---------------------------------------------------------------------------
#define ASTR 20
#define BSTR 136
__global__ __launch_bounds__(256, 2) void gemm_score_kernel(
    const float* __restrict__ A, const float* __restrict__ Bw,
    const float* __restrict__ a1, const float* __restrict__ a2) {
    __shared__ float Ahi[128 * ASTR], Alo[128 * ASTR];
    __shared__ float Bhi[16 * BSTR], Blo[16 * BSTR];
    __shared__ float a1s[32], a2s[32];

    const int tid = threadIdx.x;
    const int m0 = blockIdx.y * 128;
    const int n0 = blockIdx.x * 128;
    if (tid < 32) { a1s[tid] = a1[tid]; a2s[tid] = a2[tid]; }

    const int warp = tid >> 5, lane = tid & 31;
    const int wm = warp >> 1, wn = warp & 1;
    const int g = lane >> 2, t = lane & 3;

    float acc[2][8][4];
#pragma unroll
    for (int mt = 0; mt < 2; mt++)
#pragma unroll
        for (int nf = 0; nf < 8; nf++)
#pragma unroll
            for (int c = 0; c < 4; c++) acc[mt][nf][c] = 0.f;

    for (int k0 = 0; k0 < INF_; k0 += 16) {
        float4 va[2], vb[2];
#pragma unroll
        for (int it = 0; it < 2; it++) {
            int idx = tid + it * 256;
            va[it] = ((const float4*)A)[(size_t)(m0 + (idx >> 2)) * 64 + (k0 >> 2) + (idx & 3)];
            vb[it] = ((const float4*)Bw)[(size_t)(k0 + (idx >> 5)) * 64 + (n0 >> 2) + (idx & 31)];
        }
        __syncthreads();
#pragma unroll
        for (int it = 0; it < 2; it++) {
            int idx = tid + it * 256;
            float4 v = va[it];
            float4 hi, lo;
            hi.x = tf32f(v.x); lo.x = tf32f(v.x - hi.x);
            hi.y = tf32f(v.y); lo.y = tf32f(v.y - hi.y);
            hi.z = tf32f(v.z); lo.z = tf32f(v.z - hi.z);
            hi.w = tf32f(v.w); lo.w = tf32f(v.w - hi.w);
            int off = (idx >> 2) * ASTR + (idx & 3) * 4;
            *(float4*)&Ahi[off] = hi;
            *(float4*)&Alo[off] = lo;
            v = vb[it];
            hi.x = tf32f(v.x); lo.x = tf32f(v.x - hi.x);
            hi.y = tf32f(v.y); lo.y = tf32f(v.y - hi.y);
            hi.z = tf32f(v.z); lo.z = tf32f(v.z - hi.z);
            hi.w = tf32f(v.w); lo.w = tf32f(v.w - hi.w);
            off = (idx >> 5) * BSTR + (idx & 31) * 4;
            *(float4*)&Bhi[off] = hi;
            *(float4*)&Blo[off] = lo;
        }
        __syncthreads();
#pragma unroll
        for (int k8 = 0; k8 < 2; k8++) {
            const int kk = k8 * 8 + t;
            float ah[2][4], al[2][4];
#pragma unroll
            for (int mt = 0; mt < 2; mt++) {
                int r = (wm * 32 + mt * 16 + g) * ASTR;
                ah[mt][0] = Ahi[r + kk];
                ah[mt][1] = Ahi[r + 8 * ASTR + kk];
                ah[mt][2] = Ahi[r + kk + 4];
                ah[mt][3] = Ahi[r + 8 * ASTR + kk + 4];
                al[mt][0] = Alo[r + kk];
                al[mt][1] = Alo[r + 8 * ASTR + kk];
                al[mt][2] = Alo[r + kk + 4];
                al[mt][3] = Alo[r + 8 * ASTR + kk + 4];
            }
#pragma unroll
            for (int nf = 0; nf < 8; nf++) {
                int c = wn * 64 + nf * 8 + g;
                float bh0 = Bhi[kk * BSTR + c];
                float bh1 = Bhi[(kk + 4) * BSTR + c];
                float bl0 = Blo[kk * BSTR + c];
                float bl1 = Blo[(kk + 4) * BSTR + c];
#pragma unroll
                for (int mt = 0; mt < 2; mt++) {
                    mma_tf32(acc[mt][nf], ah[mt][0], ah[mt][1], ah[mt][2], ah[mt][3], bh0, bh1);
                    mma_tf32(acc[mt][nf], ah[mt][0], ah[mt][1], ah[mt][2], ah[mt][3], bl0, bl1);
                    mma_tf32(acc[mt][nf], al[mt][0], al[mt][1], al[mt][2], al[mt][3], bh0, bh1);
                }
            }
        }
    }

    // ---- epilogue: scores (fp32) + permuted tf32 Wh store ----
    const int hb = (n0 >> 5) + wn * 2;
#pragma unroll
    for (int mt = 0; mt < 2; mt++) {
        float pA1[2] = {0.f, 0.f}, pA2[2] = {0.f, 0.f};
        float pB1[2] = {0.f, 0.f}, pB2[2] = {0.f, 0.f};
#pragma unroll
        for (int nf = 0; nf < 8; nf++) {
            int d0 = (nf * 8 + t * 2) & 31;
            int hh = nf >> 2;
            float c0 = acc[mt][nf][0], c1 = acc[mt][nf][1];
            float c2 = acc[mt][nf][2], c3 = acc[mt][nf][3];
            pA1[hh] += c0 * a1s[d0] + c1 * a1s[d0 + 1];
            pA2[hh] += c0 * a2s[d0] + c1 * a2s[d0 + 1];
            pB1[hh] += c2 * a1s[d0] + c3 * a1s[d0 + 1];
            pB2[hh] += c2 * a2s[d0] + c3 * a2s[d0 + 1];
        }
#pragma unroll
        for (int hh = 0; hh < 2; hh++) {
            pA1[hh] += __shfl_xor_sync(0xffffffffu, pA1[hh], 1);
            pA1[hh] += __shfl_xor_sync(0xffffffffu, pA1[hh], 2);
            pA2[hh] += __shfl_xor_sync(0xffffffffu, pA2[hh], 1);
            pA2[hh] += __shfl_xor_sync(0xffffffffu, pA2[hh], 2);
            pB1[hh] += __shfl_xor_sync(0xffffffffu, pB1[hh], 1);
            pB1[hh] += __shfl_xor_sync(0xffffffffu, pB1[hh], 2);
            pB2[hh] += __shfl_xor_sync(0xffffffffu, pB2[hh], 1);
            pB2[hh] += __shfl_xor_sync(0xffffffffu, pB2[hh], 2);
        }
        int rA = m0 + wm * 32 + mt * 16 + g;
        int rB = rA + 8;
        if (t == 0) {
            g_s1[(size_t)rA * 8 + hb]     = pA1[0] * LOG2E;
            g_s1[(size_t)rA * 8 + hb + 1] = pA1[1] * LOG2E;
            g_s2[(size_t)rA * 8 + hb]     = pA2[0] * LOG2E;
            g_s2[(size_t)rA * 8 + hb + 1] = pA2[1] * LOG2E;
            g_s1[(size_t)rB * 8 + hb]     = pB1[0] * LOG2E;
            g_s1[(size_t)rB * 8 + hb + 1] = pB1[1] * LOG2E;
            g_s2[(size_t)rB * 8 + hb]     = pB2[0] * LOG2E;
            g_s2[(size_t)rB * 8 + hb + 1] = pB2[1] * LOG2E;
        }
        // Permuted store: dim dl = nfr*8 + gr  -> pos = gr*4 + nfr.
        // c0: dl = (nf&3)*8 + 2t -> pos = 8t + (nf&3);   c1: dl+1 -> pos+4.
#pragma unroll
        for (int nf = 0; nf < 8; nf++) {
            int h_idx = wn * 2 + (nf >> 2);
            int basec = n0 + h_idx * 32 + (nf & 3) + 8 * t;
            g_Wh[(size_t)rA * 256 + basec]     = tf32f(acc[mt][nf][0]);
            g_Wh[(size_t)rA * 256 + basec + 4] = tf32f(acc[mt][nf][1]);
            g_Wh[(size_t)rB * 256 + basec]     = tf32f(acc[mt][nf][2]);
            g_Wh[(size_t)rB * 256 + basec + 4] = tf32f(acc[mt][nf][3]);
        }
    }
}

// ---------------------------------------------------------------------------
// K2: fused attention via mma.sync tf32 + softmax + LayerNorm + ELU
// SMEM layout (float units):
//   [0]     s2s    4096
//   [4096]  embT   512    (8 heads x 64; entry>=50 = -12000 mask)
//   [4608]  gs     256
//   [4864]  bs     256
//   [5120]  s1s    256
//   [5376]  denS   256
//   [5632]  codesS 576 u32 (32 rows x 18-padded words)
//   [6208]  WhS    64 x 264 u32 (permuted tf32)  -- aliased as outS f32
// total 23104 floats = 92416 B  (x2 blocks = 184832 <= 228KB)
// ---------------------------------------------------------------------------
__global__ void __launch_bounds__(512, 2)
attn_kernel(const int* __restrict__ adj, const int* __restrict__ et,
            const float* __restrict__ edge_emb,
            const float* __restrict__ gamma, const float* __restrict__ beta,
            float* __restrict__ out) {
    extern __shared__ float sm[];
    float* s2s  = sm;
    float* embT = sm + 4096;
    float* gs   = sm + 4608;
    float* bs   = sm + 4864;
    float* s1s  = sm + 5120;
    float* denS = sm + 5376;
    unsigned int* codesS = (unsigned int*)(sm + 5632);
    unsigned int* WhS    = (unsigned int*)(sm + 6208);
    float*        outS   = (float*)(sm + 6208);

    const int b     = blockIdx.y;
    const int iBase = blockIdx.x * IT_;
    const int tid   = threadIdx.x;
    const int warp  = tid >> 5, lane = tid & 31;

    const float* s2g = g_s2 + (size_t)b * N_ * H_;
    for (int i = tid; i < N_ * H_; i += 512) s2s[i] = s2g[i];
    {
        int h = tid >> 6, e = tid & 63;
        embT[tid] = (e < NET_) ? edge_emb[e * H_ + h] * LOG2E : -12000.0f;
    }
    if (tid < 256) { gs[tid] = gamma[tid]; bs[tid] = beta[tid]; }
    if (tid < IT_ * H_) s1s[tid] = g_s1[((size_t)b * N_ + iBase) * H_ + tid];

    const int it = warp >> 3;
    const int h  = warp & 7;
    const int g  = lane >> 2;
    const int t  = lane & 3;
    const int r0 = it * 16 + g;
    const int r1 = r0 + 8;
    const int sh = t * 8;
    const float* embH = embT + h * 64;

    __syncthreads();
    const float s1a = s1s[r0 * 8 + h];
    const float s1b = s1s[r1 * 8 + h];

    float acc[4][4];
#pragma unroll
    for (int nf = 0; nf < 4; nf++)
#pragma unroll
        for (int k = 0; k < 4; k++) acc[nf][k] = 0.f;
    float den0 = 0.f, den1 = 0.f;

    const int4* adjRow = (const int4*)(adj + ((size_t)(b * N_ + iBase)) * N_);
    const int4* etRow  = (const int4*)(et  + ((size_t)(b * N_ + iBase)) * N_);

    for (int jc = 0; jc < N_; jc += CJ_) {
        __syncthreads();
        const uint4* whg = (const uint4*)(g_Wh + ((size_t)b * N_ + jc) * 256);
        for (int idx = tid; idx < 64 * 64; idx += 512) {
            int rr = idx >> 6, cc = idx & 63;
            *(uint4*)&WhS[rr * WSTR + cc * 4] = whg[idx];
        }
        {
            int rr = tid >> 4, ww = tid & 15;
            int4 a4 = adjRow[rr * (N_ / 4) + (jc >> 2) + ww];
            int4 t4 = etRow[rr * (N_ / 4) + (jc >> 2) + ww];
            unsigned int c0 = a4.x ? (unsigned int)t4.x : 50u;
            unsigned int c1 = a4.y ? (unsigned int)t4.y : 50u;
            unsigned int c2 = a4.z ? (unsigned int)t4.z : 50u;
            unsigned int c3 = a4.w ? (unsigned int)t4.w : 50u;
            codesS[rr * 18 + ww] = c0 | (c1 << 8) | (c2 << 16) | (c3 << 24);
        }
        __syncthreads();

        const unsigned int* cR0 = codesS + r0 * 18;
        const unsigned int* cR1 = codesS + r1 * 18;
#pragma unroll
        for (int k8 = 0; k8 < 8; k8++) {
            const int jl  = k8 * 8;
            const int jgl = jc + jl;
            uint2 cw0 = *(const uint2*)&cR0[k8 * 2];   // row r0, cols jl..jl+7
            uint2 cw1 = *(const uint2*)&cR1[k8 * 2];   // row r1

            float s2c0 = s2s[(jgl + t) * 8 + h];
            float s2c1 = s2s[(jgl + t + 4) * 8 + h];

            float e00 = s1a + s2c0 + embH[(cw0.x >> sh) & 0xff];
            float e10 = s1b + s2c0 + embH[(cw1.x >> sh) & 0xff];
            float e01 = s1a + s2c1 + embH[(cw0.y >> sh) & 0xff];
            float e11 = s1b + s2c1 + embH[(cw1.y >> sh) & 0xff];
            e00 = fmaxf(e00, 0.2f * e00);
            e10 = fmaxf(e10, 0.2f * e10);
            e01 = fmaxf(e01, 0.2f * e01);
            e11 = fmaxf(e11, 0.2f * e11);
            float w00 = ex2f(e00);
            float w10 = ex2f(e10);
            float w01 = ex2f(e01);
            float w11 = ex2f(e11);
            den0 += w00 + w01;
            den1 += w10 + w11;

            float a0 = tf32f(w00), a1f = tf32f(w10);
            float a2f = tf32f(w01), a3f = tf32f(w11);

            // B fragments: 4 nf values contiguous thanks to permuted layout
            uint4 B0v = *(const uint4*)&WhS[(jl + t) * WSTR + h * 32 + g * 4];
            uint4 B1v = *(const uint4*)&WhS[(jl + t + 4) * WSTR + h * 32 + g * 4];
            mma_tf32(acc[0], a0, a1f, a2f, a3f, __uint_as_float(B0v.x), __uint_as_float(B1v.x));
            mma_tf32(acc[1], a0, a1f, a2f, a3f, __uint_as_float(B0v.y), __uint_as_float(B1v.y));
            mma_tf32(acc[2], a0, a1f, a2f, a3f, __uint_as_float(B0v.z), __uint_as_float(B1v.z));
            mma_tf32(acc[3], a0, a1f, a2f, a3f, __uint_as_float(B0v.w), __uint_as_float(B1v.w));
        }
    }

    den0 += __shfl_xor_sync(0xffffffffu, den0, 1);
    den0 += __shfl_xor_sync(0xffffffffu, den0, 2);
    den1 += __shfl_xor_sync(0xffffffffu, den1, 1);
    den1 += __shfl_xor_sync(0xffffffffu, den1, 2);

    __syncthreads();
    if (t == 0) {
        denS[r0 * 8 + h] = den0;
        denS[r1 * 8 + h] = den1;
    }
    // D fragment: tile nf, col t*2 -> dim nf*8 + t*2 (same as before)
#pragma unroll
    for (int nf = 0; nf < 4; nf++) {
        int col = h * 32 + nf * 8 + t * 2;
        *(float2*)&outS[r0 * WSTR + col] = make_float2(acc[nf][0], acc[nf][1]);
        *(float2*)&outS[r1 * WSTR + col] = make_float2(acc[nf][2], acc[nf][3]);
    }
    __syncthreads();

#pragma unroll
    for (int rr = warp * 2; rr < warp * 2 + 2; rr++) {
        float inv = 1.0f / denS[rr * 8 + (lane >> 2)];
        float4 v0 = *(float4*)&outS[rr * WSTR + lane * 8];
        float4 v1 = *(float4*)&outS[rr * WSTR + lane * 8 + 4];
        float v[8] = {v0.x, v0.y, v0.z, v0.w, v1.x, v1.y, v1.z, v1.w};
        float s = 0.f, q = 0.f;
#pragma unroll
        for (int k = 0; k < 8; k++) {
            v[k] *= inv;
            s += v[k];
            q = fmaf(v[k], v[k], q);
        }
#pragma unroll
        for (int off = 16; off; off >>= 1) {
            s += __shfl_xor_sync(0xffffffffu, s, off);
            q += __shfl_xor_sync(0xffffffffu, q, off);
        }
        float mu   = s * (1.0f / 256.0f);
        float var  = q * (1.0f / 256.0f) - mu * mu;
        float rstd = rsqrtf(var + 1e-5f);
        float o[8];
#pragma unroll
        for (int k = 0; k < 8; k++) {
            int d = lane * 8 + k;
            float y = (v[k] - mu) * rstd * gs[d] + bs[d];
            o[k] = (y > 0.f) ? y : (__expf(y) - 1.0f);
        }
        float4* op = (float4*)(out + ((size_t)b * N_ + iBase + rr) * 256);
        op[lane * 2]     = make_float4(o[0], o[1], o[2], o[3]);
        op[lane * 2 + 1] = make_float4(o[4], o[5], o[6], o[7]);
    }
}

// ---------------------------------------------------------------------------
extern "C" void kernel_launch(void* const* d_in, const int* in_sizes, int n_in,
                              void* d_out, int out_size) {
    const float* x     = (const float*)d_in[0];
    const int*   adj   = (const int*)d_in[1];
    const int*   et    = (const int*)d_in[2];
    const float* W     = (const float*)d_in[3];
    const float* a1    = (const float*)d_in[4];
    const float* a2    = (const float*)d_in[5];
    const float* eemb  = (const float*)d_in[6];
    const float* gamma = (const float*)d_in[7];
    const float* beta  = (const float*)d_in[8];
    float* out = (float*)d_out;

    // K1: Wh = x @ W (3xTF32 tensor cores) + fused s1/s2 scores
    {
        dim3 grid(OUTF_ / 128, (B_ * N_) / 128);
        gemm_score_kernel<<<grid, 256>>>(x, W, a1, a2);
    }
    // K2: fused attention (tensor cores) + LN + ELU
    {
        const int smemBytes = 23104 * 4;  // 92416
        cudaFuncSetAttribute(attn_kernel, cudaFuncAttributeMaxDynamicSharedMemorySize,
                             smemBytes);
        dim3 grid(N_ / IT_, B_);
        attn_kernel<<<grid, 512, smemBytes>>>(adj, et, eemb, gamma, beta, out);
    }
}

// round 7
// speedup vs baseline: 2.1161x; 1.0754x over previous
#include <cuda_runtime.h>
#include <cstdint>

#define B_    16
#define N_    512
#define INF_  256
#define OUTF_ 256
#define H_    8
#define NET_  50
#define LOG2E 1.4426950408889634f
#define IT_   32      // i-rows per block (attn)
#define CJ_   32      // j-chunk (attn)
#define WSTR  264     // WhS row stride (u32)
#define WBUF  (CJ_ * WSTR)   // 8448

// SMEM offsets (float units)
#define OFF_S2    0
#define OFF_EMB   4096
#define OFF_G     4608
#define OFF_B     4864
#define OFF_S1    5120
#define OFF_DEN   5376
#define OFF_CODES 5632              // 2 x 320 u32
#define OFF_ADJ   6272              // 2 x 256 uint4 = 2048 u32
#define OFF_ET    8320              // 2048 u32
#define OFF_WH    10368             // 2 x 8448 u32
#define SMEM_FLOATS (OFF_WH + 2 * WBUF)   // 27264 -> 109056 B

// Scratch (allocation-free rule: __device__ globals)
// g_Wh: row-major [row][256]; within each head's 32 dims permuted:
// storage pos p = g*4 + nf  <->  dim dl = nf*8 + g.
__device__ float g_Wh[B_ * N_ * OUTF_];
__device__ float g_s1[B_ * N_ * H_];      // pre-scaled by log2e
__device__ float g_s2[B_ * N_ * H_];

// ---------------------------------------------------------------------------
__device__ __forceinline__ float ex2f(float x) {   // MUFU.EX2
    float r;
    asm("ex2.approx.f32 %0, %1;" : "=f"(r) : "f"(x));
    return r;
}
__device__ __forceinline__ float tf32f(float f) {
    unsigned int u;
    asm("cvt.rna.tf32.f32 %0, %1;" : "=r"(u) : "f"(f));
    return __uint_as_float(u);
}
__device__ __forceinline__ void mma_tf32(float acc[4], float a0, float a1f,
                                         float a2f, float a3f, float b0, float b1) {
    asm volatile(
        "mma.sync.aligned.m16n8k8.row.col.f32.tf32.tf32.f32 "
        "{%0,%1,%2,%3}, {%4,%5,%6,%7}, {%8,%9}, {%0,%1,%2,%3};"
        : "+f"(acc[0]), "+f"(acc[1]), "+f"(acc[2]), "+f"(acc[3])
        : "r"(__float_as_uint(a0)), "r"(__float_as_uint(a1f)),
          "r"(__float_as_uint(a2f)), "r"(__float_as_uint(a3f)),
          "r"(__float_as_uint(b0)), "r"(__float_as_uint(b1)));
}
__device__ __forceinline__ void cp_async16(unsigned int smem_addr, const void* gptr) {
    asm volatile("cp.async.cg.shared.global [%0], [%1], 16;" ::"r"(smem_addr), "l"(gptr));
}
__device__ __forceinline__ unsigned int smem_u32(const void* p) {
    unsigned int a;
    asm("{ .reg .u64 t; cvta.to.shared.u64 t, %1; cvt.u32.u64 %0, t; }" : "=r"(a) : "l"(p));
    return a;
}

// ---------------------------------------------------------------------------
// K1: Wh = x @ W via 3xTF32 tensor-core GEMM + fused s1/s2 score epilogue.
// ---------------------------------------------------------------------------
#define ASTR 20
#define BSTR 136
__global__ __launch_bounds__(256, 2) void gemm_score_kernel(
    const float* __restrict__ A, const float* __restrict__ Bw,
    const float* __restrict__ a1, const float* __restrict__ a2) {
    __shared__ float Ahi[128 * ASTR], Alo[128 * ASTR];
    __shared__ float Bhi[16 * BSTR], Blo[16 * BSTR];
    __shared__ float a1s[32], a2s[32];

    const int tid = threadIdx.x;
    const int m0 = blockIdx.y * 128;
    const int n0 = blockIdx.x * 128;
    if (tid < 32) { a1s[tid] = a1[tid]; a2s[tid] = a2[tid]; }

    const int warp = tid >> 5, lane = tid & 31;
    const int wm = warp >> 1, wn = warp & 1;
    const int g = lane >> 2, t = lane & 3;

    float acc[2][8][4];
#pragma unroll
    for (int mt = 0; mt < 2; mt++)
#pragma unroll
        for (int nf = 0; nf < 8; nf++)
#pragma unroll
            for (int c = 0; c < 4; c++) acc[mt][nf][c] = 0.f;

    for (int k0 = 0; k0 < INF_; k0 += 16) {
        float4 va[2], vb[2];
#pragma unroll
        for (int it = 0; it < 2; it++) {
            int idx = tid + it * 256;
            va[it] = ((const float4*)A)[(size_t)(m0 + (idx >> 2)) * 64 + (k0 >> 2) + (idx & 3)];
            vb[it] = ((const float4*)Bw)[(size_t)(k0 + (idx >> 5)) * 64 + (n0 >> 2) + (idx & 31)];
        }
        __syncthreads();
#pragma unroll
        for (int it = 0; it < 2; it++) {
            int idx = tid + it * 256;
            float4 v = va[it];
            float4 hi, lo;
            hi.x = tf32f(v.x); lo.x = tf32f(v.x - hi.x);
            hi.y = tf32f(v.y); lo.y = tf32f(v.y - hi.y);
            hi.z = tf32f(v.z); lo.z = tf32f(v.z - hi.z);
            hi.w = tf32f(v.w); lo.w = tf32f(v.w - hi.w);
            int off = (idx >> 2) * ASTR + (idx & 3) * 4;
            *(float4*)&Ahi[off] = hi;
            *(float4*)&Alo[off] = lo;
            v = vb[it];
            hi.x = tf32f(v.x); lo.x = tf32f(v.x - hi.x);
            hi.y = tf32f(v.y); lo.y = tf32f(v.y - hi.y);
            hi.z = tf32f(v.z); lo.z = tf32f(v.z - hi.z);
            hi.w = tf32f(v.w); lo.w = tf32f(v.w - hi.w);
            off = (idx >> 5) * BSTR + (idx & 31) * 4;
            *(float4*)&Bhi[off] = hi;
            *(float4*)&Blo[off] = lo;
        }
        __syncthreads();
#pragma unroll
        for (int k8 = 0; k8 < 2; k8++) {
            const int kk = k8 * 8 + t;
            float ah[2][4], al[2][4];
#pragma unroll
            for (int mt = 0; mt < 2; mt++) {
                int r = (wm * 32 + mt * 16 + g) * ASTR;
                ah[mt][0] = Ahi[r + kk];
                ah[mt][1] = Ahi[r + 8 * ASTR + kk];
                ah[mt][2] = Ahi[r + kk + 4];
                ah[mt][3] = Ahi[r + 8 * ASTR + kk + 4];
                al[mt][0] = Alo[r + kk];
                al[mt][1] = Alo[r + 8 * ASTR + kk];
                al[mt][2] = Alo[r + kk + 4];
                al[mt][3] = Alo[r + 8 * ASTR + kk + 4];
            }
#pragma unroll
            for (int nf = 0; nf < 8; nf++) {
                int c = wn * 64 + nf * 8 + g;
                float bh0 = Bhi[kk * BSTR + c];
                float bh1 = Bhi[(kk + 4) * BSTR + c];
                float bl0 = Blo[kk * BSTR + c];
                float bl1 = Blo[(kk + 4) * BSTR + c];
#pragma unroll
                for (int mt = 0; mt < 2; mt++) {
                    mma_tf32(acc[mt][nf], ah[mt][0], ah[mt][1], ah[mt][2], ah[mt][3], bh0, bh1);
                    mma_tf32(acc[mt][nf], ah[mt][0], ah[mt][1], ah[mt][2], ah[mt][3], bl0, bl1);
                    mma_tf32(acc[mt][nf], al[mt][0], al[mt][1], al[mt][2], al[mt][3], bh0, bh1);
                }
            }
        }
    }

    const int hb = (n0 >> 5) + wn * 2;
#pragma unroll
    for (int mt = 0; mt < 2; mt++) {
        float pA1[2] = {0.f, 0.f}, pA2[2] = {0.f, 0.f};
        float pB1[2] = {0.f, 0.f}, pB2[2] = {0.f, 0.f};
#pragma unroll
        for (int nf = 0; nf < 8; nf++) {
            int d0 = (nf * 8 + t * 2) & 31;
            int hh = nf >> 2;
            float c0 = acc[mt][nf][0], c1 = acc[mt][nf][1];
            float c2 = acc[mt][nf][2], c3 = acc[mt][nf][3];
            pA1[hh] += c0 * a1s[d0] + c1 * a1s[d0 + 1];
            pA2[hh] += c0 * a2s[d0] + c1 * a2s[d0 + 1];
            pB1[hh] += c2 * a1s[d0] + c3 * a1s[d0 + 1];
            pB2[hh] += c2 * a2s[d0] + c3 * a2s[d0 + 1];
        }
#pragma unroll
        for (int hh = 0; hh < 2; hh++) {
            pA1[hh] += __shfl_xor_sync(0xffffffffu, pA1[hh], 1);
            pA1[hh] += __shfl_xor_sync(0xffffffffu, pA1[hh], 2);
            pA2[hh] += __shfl_xor_sync(0xffffffffu, pA2[hh], 1);
            pA2[hh] += __shfl_xor_sync(0xffffffffu, pA2[hh], 2);
            pB1[hh] += __shfl_xor_sync(0xffffffffu, pB1[hh], 1);
            pB1[hh] += __shfl_xor_sync(0xffffffffu, pB1[hh], 2);
            pB2[hh] += __shfl_xor_sync(0xffffffffu, pB2[hh], 1);
            pB2[hh] += __shfl_xor_sync(0xffffffffu, pB2[hh], 2);
        }
        int rA = m0 + wm * 32 + mt * 16 + g;
        int rB = rA + 8;
        if (t == 0) {
            g_s1[(size_t)rA * 8 + hb]     = pA1[0] * LOG2E;
            g_s1[(size_t)rA * 8 + hb + 1] = pA1[1] * LOG2E;
            g_s2[(size_t)rA * 8 + hb]     = pA2[0] * LOG2E;
            g_s2[(size_t)rA * 8 + hb + 1] = pA2[1] * LOG2E;
            g_s1[(size_t)rB * 8 + hb]     = pB1[0] * LOG2E;
            g_s1[(size_t)rB * 8 + hb + 1] = pB1[1] * LOG2E;
            g_s2[(size_t)rB * 8 + hb]     = pB2[0] * LOG2E;
            g_s2[(size_t)rB * 8 + hb + 1] = pB2[1] * LOG2E;
        }
#pragma unroll
        for (int nf = 0; nf < 8; nf++) {
            int h_idx = wn * 2 + (nf >> 2);
            int basec = n0 + h_idx * 32 + (nf & 3) + 8 * t;
            g_Wh[(size_t)rA * 256 + basec]     = tf32f(acc[mt][nf][0]);
            g_Wh[(size_t)rA * 256 + basec + 4] = tf32f(acc[mt][nf][1]);
            g_Wh[(size_t)rB * 256 + basec]     = tf32f(acc[mt][nf][2]);
            g_Wh[(size_t)rB * 256 + basec + 4] = tf32f(acc[mt][nf][3]);
        }
    }
}

// ---------------------------------------------------------------------------
// K2: fused attention, cp.async double-buffered pipeline.
// Barrier discipline per iteration n:
//   sync A  : all compute of chunk n-1 (reader of buffer 1-buf) has drained
//   issue n+1 -> buffer 1-buf ; commit ; wait_group 1 (chunk n landed, per-thread)
//   sync B  : chunk n's cp.async data visible to every warp
//   pack codes (buf) ; sync C ; compute chunk n
// ---------------------------------------------------------------------------
__global__ void __launch_bounds__(512, 2)
attn_kernel(const int* __restrict__ adj, const int* __restrict__ et,
            const float* __restrict__ edge_emb,
            const float* __restrict__ gamma, const float* __restrict__ beta,
            float* __restrict__ out) {
    extern __shared__ float sm[];
    float* s2s  = sm + OFF_S2;
    float* embT = sm + OFF_EMB;
    float* gs   = sm + OFF_G;
    float* bs   = sm + OFF_B;
    float* s1s  = sm + OFF_S1;
    float* denS = sm + OFF_DEN;
    unsigned int* codesS = (unsigned int*)(sm + OFF_CODES);   // 2 x (32 x 10)
    uint4*        adjS   = (uint4*)(sm + OFF_ADJ);            // 2 x 256
    uint4*        etS    = (uint4*)(sm + OFF_ET);             // 2 x 256
    unsigned int* WhS    = (unsigned int*)(sm + OFF_WH);      // 2 x WBUF
    float*        outS   = (float*)(sm + OFF_WH);

    const int b     = blockIdx.y;
    const int iBase = blockIdx.x * IT_;
    const int tid   = threadIdx.x;
    const int warp  = tid >> 5, lane = tid & 31;

    const unsigned int adjU = smem_u32(adjS);
    const unsigned int etU  = smem_u32(etS);
    const unsigned int whU  = smem_u32(WhS);

    // one-time staging
    const float* s2g = g_s2 + (size_t)b * N_ * H_;
    for (int i = tid; i < N_ * H_; i += 512) s2s[i] = s2g[i];
    {
        int h = tid >> 6, e = tid & 63;
        embT[tid] = (e < NET_) ? edge_emb[e * H_ + h] * LOG2E : -12000.0f;
    }
    if (tid < 256) { gs[tid] = gamma[tid]; bs[tid] = beta[tid]; }
    if (tid < IT_ * H_) s1s[tid] = g_s1[((size_t)b * N_ + iBase) * H_ + tid];

    const int it = warp >> 3;
    const int h  = warp & 7;
    const int g  = lane >> 2;
    const int t  = lane & 3;
    const int r0 = it * 16 + g;
    const int r1 = r0 + 8;
    const unsigned int selA = 0x4440u | (unsigned int)t;
    const float* embH = embT + h * 64;

    const int4* adjRow = (const int4*)(adj + ((size_t)(b * N_ + iBase)) * N_);
    const int4* etRow  = (const int4*)(et  + ((size_t)(b * N_ + iBase)) * N_);
    const uint4* whg   = (const uint4*)(g_Wh + (size_t)b * N_ * 256);
    const int crr = tid >> 3, cww = tid & 7;   // code staging role (tid<256)

    // prologue: chunk 0 -> buffer 0
#pragma unroll
    for (int k2 = 0; k2 < 4; k2++) {
        int idx = tid + k2 * 512;
        int rr = idx >> 6, cc = idx & 63;
        cp_async16(whU + (unsigned)(rr * WSTR + cc * 4) * 4u, whg + idx);
    }
    if (tid < 256) {
        cp_async16(adjU + (unsigned)tid * 16u, adjRow + crr * (N_ / 4) + cww);
        cp_async16(etU + (unsigned)tid * 16u, etRow + crr * (N_ / 4) + cww);
    }
    asm volatile("cp.async.commit_group;");

    __syncthreads();
    const float s1a = s1s[r0 * 8 + h];
    const float s1b = s1s[r1 * 8 + h];

    float acc[4][4];
#pragma unroll
    for (int nf = 0; nf < 4; nf++)
#pragma unroll
        for (int k = 0; k < 4; k++) acc[nf][k] = 0.f;
    float den0 = 0.f, den1 = 0.f;

    for (int n = 0; n < 16; n++) {
        const int buf = n & 1;
        __syncthreads();   // sync A: compute of chunk n-1 (buffer 1-buf) drained
        // issue chunk n+1 into the other buffer
        if (n < 15) {
            const uint4* src = whg + (n + 1) * (CJ_ * 64);
            unsigned int dstb = whU + (unsigned)(1 - buf) * (WBUF * 4u);
#pragma unroll
            for (int k2 = 0; k2 < 4; k2++) {
                int idx = tid + k2 * 512;
                int rr = idx >> 6, cc = idx & 63;
                cp_async16(dstb + (unsigned)(rr * WSTR + cc * 4) * 4u, src + idx);
            }
            if (tid < 256) {
                unsigned int bo = (unsigned)(1 - buf) * 4096u + (unsigned)tid * 16u;
                cp_async16(adjU + bo, adjRow + crr * (N_ / 4) + (n + 1) * 8 + cww);
                cp_async16(etU + bo, etRow + crr * (N_ / 4) + (n + 1) * 8 + cww);
            }
            asm volatile("cp.async.commit_group;");
            asm volatile("cp.async.wait_group 1;");
        } else {
            asm volatile("cp.async.wait_group 0;");
        }
        __syncthreads();   // sync B: chunk n landed and visible

        // pack codes for chunk n from staged adj/et
        if (tid < 256) {
            uint4 a4 = adjS[buf * 256 + tid];
            uint4 t4 = etS[buf * 256 + tid];
            unsigned int c0 = a4.x ? t4.x : 50u;
            unsigned int c1 = a4.y ? t4.y : 50u;
            unsigned int c2 = a4.z ? t4.z : 50u;
            unsigned int c3 = a4.w ? t4.w : 50u;
            codesS[buf * 320 + crr * 10 + cww] = c0 | (c1 << 8) | (c2 << 16) | (c3 << 24);
        }
        __syncthreads();   // sync C: codes visible

        const unsigned int* whb = WhS + buf * WBUF;
        const unsigned int* cR0 = codesS + buf * 320 + r0 * 10;
        const unsigned int* cR1 = codesS + buf * 320 + r1 * 10;
        const int jc = n * CJ_;
#pragma unroll
        for (int k8 = 0; k8 < 4; k8++) {
            const int jl  = k8 * 8;
            const int jgl = jc + jl;
            uint2 cw0 = *(const uint2*)&cR0[k8 * 2];
            uint2 cw1 = *(const uint2*)&cR1[k8 * 2];

            float s2c0 = s2s[(jgl + t) * 8 + h];
            float s2c1 = s2s[(jgl + t + 4) * 8 + h];

            float e00 = s1a + s2c0 + embH[__byte_perm(cw0.x, 0, selA)];
            float e10 = s1b + s2c0 + embH[__byte_perm(cw1.x, 0, selA)];
            float e01 = s1a + s2c1 + embH[__byte_perm(cw0.y, 0, selA)];
            float e11 = s1b + s2c1 + embH[__byte_perm(cw1.y, 0, selA)];
            e00 = fmaxf(e00, 0.2f * e00);
            e10 = fmaxf(e10, 0.2f * e10);
            e01 = fmaxf(e01, 0.2f * e01);
            e11 = fmaxf(e11, 0.2f * e11);
            float w00 = ex2f(e00);
            float w10 = ex2f(e10);
            float w01 = ex2f(e01);
            float w11 = ex2f(e11);
            den0 += w00 + w01;
            den1 += w10 + w11;

            float a0 = tf32f(w00), a1f = tf32f(w10);
            float a2f = tf32f(w01), a3f = tf32f(w11);

            uint4 B0v = *(const uint4*)&whb[(jl + t) * WSTR + h * 32 + g * 4];
            uint4 B1v = *(const uint4*)&whb[(jl + t + 4) * WSTR + h * 32 + g * 4];
            mma_tf32(acc[0], a0, a1f, a2f, a3f, __uint_as_float(B0v.x), __uint_as_float(B1v.x));
            mma_tf32(acc[1], a0, a1f, a2f, a3f, __uint_as_float(B0v.y), __uint_as_float(B1v.y));
            mma_tf32(acc[2], a0, a1f, a2f, a3f, __uint_as_float(B0v.z), __uint_as_float(B1v.z));
            mma_tf32(acc[3], a0, a1f, a2f, a3f, __uint_as_float(B0v.w), __uint_as_float(B1v.w));
        }
    }

    den0 += __shfl_xor_sync(0xffffffffu, den0, 1);
    den0 += __shfl_xor_sync(0xffffffffu, den0, 2);
    den1 += __shfl_xor_sync(0xffffffffu, den1, 1);
    den1 += __shfl_xor_sync(0xffffffffu, den1, 2);

    __syncthreads();  // all MMA reads of WhS done; alias as outS
    if (t == 0) {
        denS[r0 * 8 + h] = den0;
        denS[r1 * 8 + h] = den1;
    }
#pragma unroll
    for (int nf = 0; nf < 4; nf++) {
        int col = h * 32 + nf * 8 + t * 2;
        *(float2*)&outS[r0 * WSTR + col] = make_float2(acc[nf][0], acc[nf][1]);
        *(float2*)&outS[r1 * WSTR + col] = make_float2(acc[nf][2], acc[nf][3]);
    }
    __syncthreads();

#pragma unroll
    for (int rr = warp * 2; rr < warp * 2 + 2; rr++) {
        float inv = 1.0f / denS[rr * 8 + (lane >> 2)];
        float4 v0 = *(float4*)&outS[rr * WSTR + lane * 8];
        float4 v1 = *(float4*)&outS[rr * WSTR + lane * 8 + 4];
        float v[8] = {v0.x, v0.y, v0.z, v0.w, v1.x, v1.y, v1.z, v1.w};
        float s = 0.f, q = 0.f;
#pragma unroll
        for (int k = 0; k < 8; k++) {
            v[k] *= inv;
            s += v[k];
            q = fmaf(v[k], v[k], q);
        }
#pragma unroll
        for (int off = 16; off; off >>= 1) {
            s += __shfl_xor_sync(0xffffffffu, s, off);
            q += __shfl_xor_sync(0xffffffffu, q, off);
        }
        float mu   = s * (1.0f / 256.0f);
        float var  = q * (1.0f / 256.0f) - mu * mu;
        float rstd = rsqrtf(var + 1e-5f);
        float o[8];
#pragma unroll
        for (int k = 0; k < 8; k++) {
            int d = lane * 8 + k;
            float y = (v[k] - mu) * rstd * gs[d] + bs[d];
            o[k] = (y > 0.f) ? y : (__expf(y) - 1.0f);
        }
        float4* op = (float4*)(out + ((size_t)b * N_ + iBase + rr) * 256);
        op[lane * 2]     = make_float4(o[0], o[1], o[2], o[3]);
        op[lane * 2 + 1] = make_float4(o[4], o[5], o[6], o[7]);
    }
}

// ---------------------------------------------------------------------------
extern "C" void kernel_launch(void* const* d_in, const int* in_sizes, int n_in,
                              void* d_out, int out_size) {
    (void)in_sizes; (void)n_in; (void)out_size;
    const float* x     = (const float*)d_in[0];
    const int*   adj   = (const int*)d_in[1];
    const int*   et    = (const int*)d_in[2];
    const float* W     = (const float*)d_in[3];
    const float* a1    = (const float*)d_in[4];
    const float* a2    = (const float*)d_in[5];
    const float* eemb  = (const float*)d_in[6];
    const float* gamma = (const float*)d_in[7];
    const float* beta  = (const float*)d_in[8];
    float* out = (float*)d_out;

    // K1: Wh = x @ W (3xTF32 tensor cores) + fused s1/s2 scores
    {
        dim3 grid(OUTF_ / 128, (B_ * N_) / 128);
        gemm_score_kernel<<<grid, 256>>>(x, W, a1, a2);
    }
    // K2: fused attention (tensor cores) + LN + ELU
    {
        const int smemBytes = SMEM_FLOATS * 4;  // 109056
        cudaFuncSetAttribute(attn_kernel, cudaFuncAttributeMaxDynamicSharedMemorySize,
                             smemBytes);
        dim3 grid(N_ / IT_, B_);
        attn_kernel<<<grid, 512, smemBytes>>>(adj, et, eemb, gamma, beta, out);
    }
}

// round 8
// speedup vs baseline: 2.1655x; 1.0233x over previous
#include <cuda_runtime.h>
#include <cstdint>

#define B_    16
#define N_    512
#define INF_  256
#define OUTF_ 256
#define H_    8
#define NET_  50
#define LOG2E 1.4426950408889634f
#define IT_   32      // i-rows per block (attn)
#define CJ_   32      // j-chunk (attn)
#define WSTR  264     // WhS row stride (u32)
#define WBUF  (CJ_ * WSTR)   // 8448

// SMEM offsets (float units)
#define OFF_S2    0
#define OFF_EMB   4096
#define OFF_G     4608
#define OFF_B     4864
#define OFF_S1    5120
#define OFF_DEN   5376
#define OFF_CODES 5632              // 2 x 384 u32 (32 rows x 12-padded, 16B-aligned)
#define OFF_ADJ   6400              // 2 x 256 uint4 = 2048 u32
#define OFF_ET    8448              // 2048 u32
#define OFF_WH    10496             // 2 x 8448 u32
#define SMEM_FLOATS (OFF_WH + 2 * WBUF)   // 27392 -> 109568 B

// Scratch (allocation-free rule: __device__ globals)
// g_Wh: row-major [row][256]; within each head's 32 dims permuted:
// storage pos p = g*4 + nf  <->  dim dl = nf*8 + g.
__device__ float g_Wh[B_ * N_ * OUTF_];
__device__ float g_s1[B_ * N_ * H_];      // pre-scaled by log2e
__device__ float g_s2[B_ * N_ * H_];

// ---------------------------------------------------------------------------
__device__ __forceinline__ float ex2f(float x) {   // MUFU.EX2
    float r;
    asm("ex2.approx.f32 %0, %1;" : "=f"(r) : "f"(x));
    return r;
}
__device__ __forceinline__ float tf32f(float f) {
    unsigned int u;
    asm("cvt.rna.tf32.f32 %0, %1;" : "=r"(u) : "f"(f));
    return __uint_as_float(u);
}
__device__ __forceinline__ void mma_tf32(float acc[4], float a0, float a1f,
                                         float a2f, float a3f, float b0, float b1) {
    asm volatile(
        "mma.sync.aligned.m16n8k8.row.col.f32.tf32.tf32.f32 "
        "{%0,%1,%2,%3}, {%4,%5,%6,%7}, {%8,%9}, {%0,%1,%2,%3};"
        : "+f"(acc[0]), "+f"(acc[1]), "+f"(acc[2]), "+f"(acc[3])
        : "r"(__float_as_uint(a0)), "r"(__float_as_uint(a1f)),
          "r"(__float_as_uint(a2f)), "r"(__float_as_uint(a3f)),
          "r"(__float_as_uint(b0)), "r"(__float_as_uint(b1)));
}
__device__ __forceinline__ void cp_async16(unsigned int smem_addr, const void* gptr) {
    asm volatile("cp.async.cg.shared.global [%0], [%1], 16;" ::"r"(smem_addr), "l"(gptr));
}
__device__ __forceinline__ unsigned int smem_u32(const void* p) {
    unsigned int a;
    asm("{ .reg .u64 t; cvta.to.shared.u64 t, %1; cvt.u32.u64 %0, t; }" : "=r"(a) : "l"(p));
    return a;
}

// ---------------------------------------------------------------------------
// K1: Wh = x @ W via 2xTF32-split tensor-core GEMM (A split hi/lo, W rounded)
// + fused s1/s2 score epilogue. Next-chunk LDG issued before MMA section.
// ---------------------------------------------------------------------------
#define ASTR 20
#define BSTR 136
__global__ __launch_bounds__(256, 2) void gemm_score_kernel(
    const float* __restrict__ A, const float* __restrict__ Bw,
    const float* __restrict__ a1, const float* __restrict__ a2) {
    __shared__ float Ahi[128 * ASTR], Alo[128 * ASTR];
    __shared__ float Bs[16 * BSTR];
    __shared__ float a1s[32], a2s[32];

    const int tid = threadIdx.x;
    const int m0 = blockIdx.y * 128;
    const int n0 = blockIdx.x * 128;
    if (tid < 32) { a1s[tid] = a1[tid]; a2s[tid] = a2[tid]; }

    const int warp = tid >> 5, lane = tid & 31;
    const int wm = warp >> 1, wn = warp & 1;
    const int g = lane >> 2, t = lane & 3;

    float acc[2][8][4];
#pragma unroll
    for (int mt = 0; mt < 2; mt++)
#pragma unroll
        for (int nf = 0; nf < 8; nf++)
#pragma unroll
            for (int c = 0; c < 4; c++) acc[mt][nf][c] = 0.f;

    float4 va[2], vb[2];
#pragma unroll
    for (int it = 0; it < 2; it++) {
        int idx = tid + it * 256;
        va[it] = ((const float4*)A)[(size_t)(m0 + (idx >> 2)) * 64 + (idx & 3)];
        vb[it] = ((const float4*)Bw)[(size_t)(idx >> 5) * 64 + (n0 >> 2) + (idx & 31)];
    }

    for (int k0 = 0; k0 < INF_; k0 += 16) {
        __syncthreads();   // previous chunk's smem readers done
#pragma unroll
        for (int it = 0; it < 2; it++) {
            int idx = tid + it * 256;
            float4 v = va[it];
            float4 hi, lo;
            hi.x = tf32f(v.x); lo.x = tf32f(v.x - hi.x);
            hi.y = tf32f(v.y); lo.y = tf32f(v.y - hi.y);
            hi.z = tf32f(v.z); lo.z = tf32f(v.z - hi.z);
            hi.w = tf32f(v.w); lo.w = tf32f(v.w - hi.w);
            int off = (idx >> 2) * ASTR + (idx & 3) * 4;
            *(float4*)&Ahi[off] = hi;
            *(float4*)&Alo[off] = lo;
            v = vb[it];
            hi.x = tf32f(v.x);
            hi.y = tf32f(v.y);
            hi.z = tf32f(v.z);
            hi.w = tf32f(v.w);
            *(float4*)&Bs[(idx >> 5) * BSTR + (idx & 31) * 4] = hi;
        }
        __syncthreads();
        // issue next chunk's LDGs; they complete under the MMA section
        if (k0 + 16 < INF_) {
#pragma unroll
            for (int it = 0; it < 2; it++) {
                int idx = tid + it * 256;
                va[it] = ((const float4*)A)[(size_t)(m0 + (idx >> 2)) * 64 +
                                            ((k0 + 16) >> 2) + (idx & 3)];
                vb[it] = ((const float4*)Bw)[(size_t)(k0 + 16 + (idx >> 5)) * 64 +
                                             (n0 >> 2) + (idx & 31)];
            }
        }
#pragma unroll
        for (int k8 = 0; k8 < 2; k8++) {
            const int kk = k8 * 8 + t;
            float ah[2][4], al[2][4];
#pragma unroll
            for (int mt = 0; mt < 2; mt++) {
                int r = (wm * 32 + mt * 16 + g) * ASTR;
                ah[mt][0] = Ahi[r + kk];
                ah[mt][1] = Ahi[r + 8 * ASTR + kk];
                ah[mt][2] = Ahi[r + kk + 4];
                ah[mt][3] = Ahi[r + 8 * ASTR + kk + 4];
                al[mt][0] = Alo[r + kk];
                al[mt][1] = Alo[r + 8 * ASTR + kk];
                al[mt][2] = Alo[r + kk + 4];
                al[mt][3] = Alo[r + 8 * ASTR + kk + 4];
            }
#pragma unroll
            for (int nf = 0; nf < 8; nf++) {
                int c = wn * 64 + nf * 8 + g;
                float bh0 = Bs[kk * BSTR + c];
                float bh1 = Bs[(kk + 4) * BSTR + c];
#pragma unroll
                for (int mt = 0; mt < 2; mt++) {
                    mma_tf32(acc[mt][nf], ah[mt][0], ah[mt][1], ah[mt][2], ah[mt][3], bh0, bh1);
                    mma_tf32(acc[mt][nf], al[mt][0], al[mt][1], al[mt][2], al[mt][3], bh0, bh1);
                }
            }
        }
    }

    const int hb = (n0 >> 5) + wn * 2;
#pragma unroll
    for (int mt = 0; mt < 2; mt++) {
        float pA1[2] = {0.f, 0.f}, pA2[2] = {0.f, 0.f};
        float pB1[2] = {0.f, 0.f}, pB2[2] = {0.f, 0.f};
#pragma unroll
        for (int nf = 0; nf < 8; nf++) {
            int d0 = (nf * 8 + t * 2) & 31;
            int hh = nf >> 2;
            float c0 = acc[mt][nf][0], c1 = acc[mt][nf][1];
            float c2 = acc[mt][nf][2], c3 = acc[mt][nf][3];
            pA1[hh] += c0 * a1s[d0] + c1 * a1s[d0 + 1];
            pA2[hh] += c0 * a2s[d0] + c1 * a2s[d0 + 1];
            pB1[hh] += c2 * a1s[d0] + c3 * a1s[d0 + 1];
            pB2[hh] += c2 * a2s[d0] + c3 * a2s[d0 + 1];
        }
#pragma unroll
        for (int hh = 0; hh < 2; hh++) {
            pA1[hh] += __shfl_xor_sync(0xffffffffu, pA1[hh], 1);
            pA1[hh] += __shfl_xor_sync(0xffffffffu, pA1[hh], 2);
            pA2[hh] += __shfl_xor_sync(0xffffffffu, pA2[hh], 1);
            pA2[hh] += __shfl_xor_sync(0xffffffffu, pA2[hh], 2);
            pB1[hh] += __shfl_xor_sync(0xffffffffu, pB1[hh], 1);
            pB1[hh] += __shfl_xor_sync(0xffffffffu, pB1[hh], 2);
            pB2[hh] += __shfl_xor_sync(0xffffffffu, pB2[hh], 1);
            pB2[hh] += __shfl_xor_sync(0xffffffffu, pB2[hh], 2);
        }
        int rA = m0 + wm * 32 + mt * 16 + g;
        int rB = rA + 8;
        if (t == 0) {
            g_s1[(size_t)rA * 8 + hb]     = pA1[0] * LOG2E;
            g_s1[(size_t)rA * 8 + hb + 1] = pA1[1] * LOG2E;
            g_s2[(size_t)rA * 8 + hb]     = pA2[0] * LOG2E;
            g_s2[(size_t)rA * 8 + hb + 1] = pA2[1] * LOG2E;
            g_s1[(size_t)rB * 8 + hb]     = pB1[0] * LOG2E;
            g_s1[(size_t)rB * 8 + hb + 1] = pB1[1] * LOG2E;
            g_s2[(size_t)rB * 8 + hb]     = pB2[0] * LOG2E;
            g_s2[(size_t)rB * 8 + hb + 1] = pB2[1] * LOG2E;
        }
#pragma unroll
        for (int nf = 0; nf < 8; nf++) {
            int h_idx = wn * 2 + (nf >> 2);
            int basec = n0 + h_idx * 32 + (nf & 3) + 8 * t;
            g_Wh[(size_t)rA * 256 + basec]     = tf32f(acc[mt][nf][0]);
            g_Wh[(size_t)rA * 256 + basec + 4] = tf32f(acc[mt][nf][1]);
            g_Wh[(size_t)rB * 256 + basec]     = tf32f(acc[mt][nf][2]);
            g_Wh[(size_t)rB * 256 + basec + 4] = tf32f(acc[mt][nf][3]);
        }
    }
}

// ---------------------------------------------------------------------------
// K2: fused attention, cp.async double-buffered pipeline.
// ---------------------------------------------------------------------------
__global__ void __launch_bounds__(512, 2)
attn_kernel(const int* __restrict__ adj, const int* __restrict__ et,
            const float* __restrict__ edge_emb,
            const float* __restrict__ gamma, const float* __restrict__ beta,
            float* __restrict__ out) {
    extern __shared__ float sm[];
    float* s2s  = sm + OFF_S2;
    float* embT = sm + OFF_EMB;
    float* gs   = sm + OFF_G;
    float* bs   = sm + OFF_B;
    float* s1s  = sm + OFF_S1;
    float* denS = sm + OFF_DEN;
    unsigned int* codesS = (unsigned int*)(sm + OFF_CODES);   // 2 x (32 x 12)
    uint4*        adjS   = (uint4*)(sm + OFF_ADJ);            // 2 x 256
    uint4*        etS    = (uint4*)(sm + OFF_ET);             // 2 x 256
    unsigned int* WhS    = (unsigned int*)(sm + OFF_WH);      // 2 x WBUF
    float*        outS   = (float*)(sm + OFF_WH);

    const int b     = blockIdx.y;
    const int iBase = blockIdx.x * IT_;
    const int tid   = threadIdx.x;
    const int warp  = tid >> 5, lane = tid & 31;

    const unsigned int adjU = smem_u32(adjS);
    const unsigned int etU  = smem_u32(etS);
    const unsigned int whU  = smem_u32(WhS);

    // one-time staging
    const float* s2g = g_s2 + (size_t)b * N_ * H_;
    for (int i = tid; i < N_ * H_; i += 512) s2s[i] = s2g[i];
    {
        int h = tid >> 6, e = tid & 63;
        embT[tid] = (e < NET_) ? edge_emb[e * H_ + h] * LOG2E : -12000.0f;
    }
    if (tid < 256) { gs[tid] = gamma[tid]; bs[tid] = beta[tid]; }
    if (tid < IT_ * H_) s1s[tid] = g_s1[((size_t)b * N_ + iBase) * H_ + tid];

    const int it = warp >> 3;
    const int h  = warp & 7;
    const int g  = lane >> 2;
    const int t  = lane & 3;
    const int r0 = it * 16 + g;
    const int r1 = r0 + 8;
    const unsigned int selA = 0x4440u | (unsigned int)t;
    const float* embH = embT + h * 64;

    const int4* adjRow = (const int4*)(adj + ((size_t)(b * N_ + iBase)) * N_);
    const int4* etRow  = (const int4*)(et  + ((size_t)(b * N_ + iBase)) * N_);
    const uint4* whg   = (const uint4*)(g_Wh + (size_t)b * N_ * 256);
    const int crr = tid >> 3, cww = tid & 7;   // code staging role (tid<256)

    // prologue: chunk 0 -> buffer 0
#pragma unroll
    for (int k2 = 0; k2 < 4; k2++) {
        int idx = tid + k2 * 512;
        int rr = idx >> 6, cc = idx & 63;
        cp_async16(whU + (unsigned)(rr * WSTR + cc * 4) * 4u, whg + idx);
    }
    if (tid < 256) {
        cp_async16(adjU + (unsigned)tid * 16u, adjRow + crr * (N_ / 4) + cww);
        cp_async16(etU + (unsigned)tid * 16u, etRow + crr * (N_ / 4) + cww);
    }
    asm volatile("cp.async.commit_group;");

    __syncthreads();
    const float s1a = s1s[r0 * 8 + h];
    const float s1b = s1s[r1 * 8 + h];

    float acc[4][4];
#pragma unroll
    for (int nf = 0; nf < 4; nf++)
#pragma unroll
        for (int k = 0; k < 4; k++) acc[nf][k] = 0.f;
    float den0 = 0.f, den1 = 0.f;

    for (int n = 0; n < 16; n++) {
        const int buf = n & 1;
        __syncthreads();   // sync A: compute of chunk n-1 (buffer 1-buf) drained
        if (n < 15) {
            const uint4* src = whg + (n + 1) * (CJ_ * 64);
            unsigned int dstb = whU + (unsigned)(1 - buf) * (WBUF * 4u);
#pragma unroll
            for (int k2 = 0; k2 < 4; k2++) {
                int idx = tid + k2 * 512;
                int rr = idx >> 6, cc = idx & 63;
                cp_async16(dstb + (unsigned)(rr * WSTR + cc * 4) * 4u, src + idx);
            }
            if (tid < 256) {
                unsigned int bo = (unsigned)(1 - buf) * 4096u + (unsigned)tid * 16u;
                cp_async16(adjU + bo, adjRow + crr * (N_ / 4) + (n + 1) * 8 + cww);
                cp_async16(etU + bo, etRow + crr * (N_ / 4) + (n + 1) * 8 + cww);
            }
            asm volatile("cp.async.commit_group;");
            asm volatile("cp.async.wait_group 1;");
        } else {
            asm volatile("cp.async.wait_group 0;");
        }
        __syncthreads();   // sync B: chunk n landed and visible

        // pack codes for chunk n from staged adj/et
        if (tid < 256) {
            uint4 a4 = adjS[buf * 256 + tid];
            uint4 t4 = etS[buf * 256 + tid];
            unsigned int c0 = a4.x ? t4.x : 50u;
            unsigned int c1 = a4.y ? t4.y : 50u;
            unsigned int c2 = a4.z ? t4.z : 50u;
            unsigned int c3 = a4.w ? t4.w : 50u;
            codesS[buf * 384 + crr * 12 + cww] = c0 | (c1 << 8) | (c2 << 16) | (c3 << 24);
        }
        __syncthreads();   // sync C: codes visible

        const unsigned int* whb = WhS + buf * WBUF;
        const unsigned int* cR0 = codesS + buf * 384 + r0 * 12;
        const unsigned int* cR1 = codesS + buf * 384 + r1 * 12;
        // whole-chunk code words via 2x LDS.128 per row (rows 48B -> 16B aligned)
        uint4 c0a = *(const uint4*)&cR0[0];
        uint4 c0b = *(const uint4*)&cR0[4];
        uint4 c1a = *(const uint4*)&cR1[0];
        uint4 c1b = *(const uint4*)&cR1[4];
        unsigned int cwR0[8] = {c0a.x, c0a.y, c0a.z, c0a.w, c0b.x, c0b.y, c0b.z, c0b.w};
        unsigned int cwR1[8] = {c1a.x, c1a.y, c1a.z, c1a.w, c1b.x, c1b.y, c1b.z, c1b.w};
        const int jc = n * CJ_;
#pragma unroll
        for (int k8 = 0; k8 < 4; k8++) {
            const int jl  = k8 * 8;
            const int jgl = jc + jl;

            float s2c0 = s2s[(jgl + t) * 8 + h];
            float s2c1 = s2s[(jgl + t + 4) * 8 + h];

            float e00 = s1a + s2c0 + embH[__byte_perm(cwR0[k8 * 2], 0, selA)];
            float e10 = s1b + s2c0 + embH[__byte_perm(cwR1[k8 * 2], 0, selA)];
            float e01 = s1a + s2c1 + embH[__byte_perm(cwR0[k8 * 2 + 1], 0, selA)];
            float e11 = s1b + s2c1 + embH[__byte_perm(cwR1[k8 * 2 + 1], 0, selA)];
            e00 = fmaxf(e00, 0.2f * e00);
            e10 = fmaxf(e10, 0.2f * e10);
            e01 = fmaxf(e01, 0.2f * e01);
            e11 = fmaxf(e11, 0.2f * e11);
            // convert first; accumulate den from converted weights so that
            // numerator (MMA) and denominator stay consistent
            float a0  = tf32f(ex2f(e00));
            float a1f = tf32f(ex2f(e10));
            float a2f = tf32f(ex2f(e01));
            float a3f = tf32f(ex2f(e11));
            den0 += a0 + a2f;
            den1 += a1f + a3f;

            uint4 B0v = *(const uint4*)&whb[(jl + t) * WSTR + h * 32 + g * 4];
            uint4 B1v = *(const uint4*)&whb[(jl + t + 4) * WSTR + h * 32 + g * 4];
            mma_tf32(acc[0], a0, a1f, a2f, a3f, __uint_as_float(B0v.x), __uint_as_float(B1v.x));
            mma_tf32(acc[1], a0, a1f, a2f, a3f, __uint_as_float(B0v.y), __uint_as_float(B1v.y));
            mma_tf32(acc[2], a0, a1f, a2f, a3f, __uint_as_float(B0v.z), __uint_as_float(B1v.z));
            mma_tf32(acc[3], a0, a1f, a2f, a3f, __uint_as_float(B0v.w), __uint_as_float(B1v.w));
        }
    }

    den0 += __shfl_xor_sync(0xffffffffu, den0, 1);
    den0 += __shfl_xor_sync(0xffffffffu, den0, 2);
    den1 += __shfl_xor_sync(0xffffffffu, den1, 1);
    den1 += __shfl_xor_sync(0xffffffffu, den1, 2);

    __syncthreads();  // all MMA reads of WhS done; alias as outS
    if (t == 0) {
        denS[r0 * 8 + h] = den0;
        denS[r1 * 8 + h] = den1;
    }
#pragma unroll
    for (int nf = 0; nf < 4; nf++) {
        int col = h * 32 + nf * 8 + t * 2;
        *(float2*)&outS[r0 * WSTR + col] = make_float2(acc[nf][0], acc[nf][1]);
        *(float2*)&outS[r1 * WSTR + col] = make_float2(acc[nf][2], acc[nf][3]);
    }
    __syncthreads();

#pragma unroll
    for (int rr = warp * 2; rr < warp * 2 + 2; rr++) {
        float inv = 1.0f / denS[rr * 8 + (lane >> 2)];
        float4 v0 = *(float4*)&outS[rr * WSTR + lane * 8];
        float4 v1 = *(float4*)&outS[rr * WSTR + lane * 8 + 4];
        float v[8] = {v0.x, v0.y, v0.z, v0.w, v1.x, v1.y, v1.z, v1.w};
        float s = 0.f, q = 0.f;
#pragma unroll
        for (int k = 0; k < 8; k++) {
            v[k] *= inv;
            s += v[k];
            q = fmaf(v[k], v[k], q);
        }
#pragma unroll
        for (int off = 16; off; off >>= 1) {
            s += __shfl_xor_sync(0xffffffffu, s, off);
            q += __shfl_xor_sync(0xffffffffu, q, off);
        }
        float mu   = s * (1.0f / 256.0f);
        float var  = q * (1.0f / 256.0f) - mu * mu;
        float rstd = rsqrtf(var + 1e-5f);
        float o[8];
#pragma unroll
        for (int k = 0; k < 8; k++) {
            int d = lane * 8 + k;
            float y = (v[k] - mu) * rstd * gs[d] + bs[d];
            o[k] = (y > 0.f) ? y : (__expf(y) - 1.0f);
        }
        float4* op = (float4*)(out + ((size_t)b * N_ + iBase + rr) * 256);
        op[lane * 2]     = make_float4(o[0], o[1], o[2], o[3]);
        op[lane * 2 + 1] = make_float4(o[4], o[5], o[6], o[7]);
    }
}

// ---------------------------------------------------------------------------
extern "C" void kernel_launch(void* const* d_in, const int* in_sizes, int n_in,
                              void* d_out, int out_size) {
    (void)in_sizes; (void)n_in; (void)out_size;
    const float* x     = (const float*)d_in[0];
    const int*   adj   = (const int*)d_in[1];
    const int*   et    = (const int*)d_in[2];
    const float* W     = (const float*)d_in[3];
    const float* a1    = (const float*)d_in[4];
    const float* a2    = (const float*)d_in[5];
    const float* eemb  = (const float*)d_in[6];
    const float* gamma = (const float*)d_in[7];
    const float* beta  = (const float*)d_in[8];
    float* out = (float*)d_out;

    // K1: Wh = x @ W (2xTF32 split tensor cores) + fused s1/s2 scores
    {
        dim3 grid(OUTF_ / 128, (B_ * N_) / 128);
        gemm_score_kernel<<<grid, 256>>>(x, W, a1, a2);
    }
    // K2: fused attention (tensor cores) + LN + ELU
    {
        const int smemBytes = SMEM_FLOATS * 4;  // 109568
        cudaFuncSetAttribute(attn_kernel, cudaFuncAttributeMaxDynamicSharedMemorySize,
                             smemBytes);
        dim3 grid(N_ / IT_, B_);
        attn_kernel<<<grid, 512, smemBytes>>>(adj, et, eemb, gamma, beta, out);
    }
}